// round 13
// baseline (speedup 1.0000x reference)
#include <cuda_runtime.h>
#include <cuda_fp16.h>
#include <cstdint>
#include <cstddef>

// ===========================================================================
// HyperNodeAggregation via mma.sync fp16 multi-product GEMMs (fp32 accum).
//   E_b = Wq (Wk G_b)^T + u1 bk^T + bq u2^T,  G_b = X X^T (symmetric)
//   P = softmax(E);  V = Wv X + bv 1^T;  out = V P^T
// fp32 operands split into 2 fp16 planes (residual 2^-11).
// Products: logit chain (G, Khat, E) = 3;  V = 2;  out = 1.
// R13: E-GEMM + softmax chained in 2 rounds of 2 batches (E stays L2-hot for
//      the softmax read, wave-neutral for E); transpose reads fp16 plane.
// ===========================================================================

using h16 = __half;

constexpr int NB = 4, CH = 512, ND = 4096;

// ---------------- scratch (device globals; allocation-free rule) -----------
__device__ __align__(128) h16 g_x [2][(size_t)NB * CH * ND];
__device__ __align__(128) h16 g_xt[(size_t)NB * ND * CH];      // single plane
__device__ __align__(128) h16 g_wq[2][(size_t)ND * CH];
__device__ __align__(128) h16 g_wk[2][(size_t)ND * CH];
__device__ __align__(128) h16 g_wv[2][(size_t)CH * CH];
__device__ __align__(128) h16 g_gg[2][(size_t)NB * CH * CH];
__device__ __align__(128) h16 g_kh[2][(size_t)NB * ND * CH];
__device__ __align__(128) h16 g_vv[(size_t)NB * CH * ND];      // single plane
__device__ __align__(128) h16 g_pp[(size_t)NB * ND * ND];      // single plane
__device__ __align__(128) float g_E [(size_t)NB * ND * ND];
__device__ __align__(128) float g_Gp[(size_t)32 * CH * CH];
__device__ float g_s[NB * CH], g_u1[NB * ND], g_u2[NB * ND];

// ---------------- asm helpers ----------------------------------------------
__device__ __forceinline__ uint32_t smem_to_u32(const void* p) {
    uint32_t a;
    asm("{ .reg .u64 t; cvta.to.shared.u64 t, %1; cvt.u32.u64 %0, t; }"
        : "=r"(a) : "l"(p));
    return a;
}
#define CPA16(s, g) \
    asm volatile("cp.async.cg.shared.global [%0], [%1], 16;" :: "r"(s), "l"(g) : "memory")
#define CPA_COMMIT() asm volatile("cp.async.commit_group;" ::: "memory")
#define CPA_WAIT(n)  asm volatile("cp.async.wait_group %0;" :: "n"(n) : "memory")
#define LDSM4(r0, r1, r2, r3, addr) \
    asm volatile("ldmatrix.sync.aligned.m8n8.x4.shared.b16 {%0,%1,%2,%3}, [%4];" \
        : "=r"(r0), "=r"(r1), "=r"(r2), "=r"(r3) : "r"(addr))
#define MMA_F16(d, a, bb0, bb1) \
    asm volatile("mma.sync.aligned.m16n8k16.row.col.f32.f16.f16.f32 " \
        "{%0,%1,%2,%3}, {%4,%5,%6,%7}, {%8,%9}, {%0,%1,%2,%3};" \
        : "+f"((d)[0]), "+f"((d)[1]), "+f"((d)[2]), "+f"((d)[3]) \
        : "r"((a)[0]), "r"((a)[1]), "r"((a)[2]), "r"((a)[3]), "r"(bb0), "r"(bb1))

// ===========================================================================
// tc_gemm<NPA, NPB, NSTAGE, OMODE>: C[128x256/CTA], NT GEMM, K-contig.
// Products: a0.b0  (+ a1.b0 if NPA==2)  (+ a0.b1 if NPB==2).
// BK=64 (128B rows, swizzle chunk ^= row&7). NSTAGE-deep cp.async pipeline;
// NSTAGE>=3 uses a single __syncthreads per chunk.
// 8 warps as 2(M) x 4(N); warp tile 64x64; m16n8k16 f16 mma, fp32 accum.
// OMODE: 0 fp32; 2 fp32 + rank-2 e0[m]e1[n]+e2[m]e3[n];
//        4 2-plane fp16 split store (+bias e0[m]); 5 1-plane fp16 (+bias).
// Split-K via nsplit. Requires nch >= NSTAGE-1.
// ===========================================================================
#define TILE_A  16384           // 128 rows * 128 B
#define TILE_BB 32768           // 256 rows * 128 B

template<int NPA, int NPB, int NSTAGE, int OMODE>
__global__ void __launch_bounds__(256, 1)
tc_gemm(const h16* __restrict__ a0, const h16* __restrict__ a1,
        const h16* __restrict__ b0, const h16* __restrict__ b1,
        int Ksub, int nsplit, int lda, int ldb, long long sA, long long sB,
        float* __restrict__ Cf, h16* __restrict__ c0, h16* __restrict__ c1,
        int ldc, long long sC,
        const float* __restrict__ e0, long long se0,
        const float* __restrict__ e1, const float* __restrict__ e2,
        const float* __restrict__ e3, long long se3)
{
    constexpr int STB = NPA * TILE_A + NPB * TILE_BB;   // stage bytes
    extern __shared__ __align__(1024) char smem[];
    const uint32_t sb = smem_to_u32(smem);
    const int tid = threadIdx.x, wid = tid >> 5, lane = tid & 31;
    const int bx = blockIdx.x, by = blockIdx.y, z = blockIdx.z;
    const int bat = z / nsplit, sp = z - bat * nsplit;

    // ---- cp.async geometry
    const int rr = tid >> 3;                 // 0..31
    const int qq = tid & 7;                  // 0..7
    const uint32_t sw = (uint32_t)((qq ^ (rr & 7)) << 4);
    const long long koffB = (long long)sp * Ksub * 2;

    const char* gA[2];
    const char* gB[2];
    long long rstepA, rstepB;
    {
        const long long la2 = (long long)lda * 2, lb2 = (long long)ldb * 2;
        gA[0] = (const char*)(a0 + (long long)bat * sA)
              + (long long)(by * 128) * la2 + rr * la2 + qq * 16 + koffB;
        gA[1] = (NPA == 2)
              ? (const char*)(a1 + (long long)bat * sA)
                + (long long)(by * 128) * la2 + rr * la2 + qq * 16 + koffB
              : nullptr;
        gB[0] = (const char*)(b0 + (long long)bat * sB)
              + (long long)(bx * 256) * lb2 + rr * lb2 + qq * 16 + koffB;
        gB[1] = (NPB == 2)
              ? (const char*)(b1 + (long long)bat * sB)
                + (long long)(bx * 256) * lb2 + rr * lb2 + qq * 16 + koffB
              : nullptr;
        rstepA = la2 * 32;
        rstepB = lb2 * 32;
    }

    auto load_stage = [&](int ck, int stg) {
        const uint32_t s0 = sb + stg * STB;
        #pragma unroll
        for (int t = 0; t < NPA; t++) {
            #pragma unroll
            for (int jj = 0; jj < 4; jj++) {       // A: 128 rows
                const uint32_t sa = s0 + t * TILE_A
                                  + (uint32_t)((jj * 32 + rr) * 128) + sw;
                CPA16(sa, gA[t] + jj * rstepA + (long long)ck * 128);
            }
        }
        #pragma unroll
        for (int t = 0; t < NPB; t++) {
            #pragma unroll
            for (int jj = 0; jj < 8; jj++) {       // B: 256 rows
                const uint32_t sa = s0 + NPA * TILE_A + t * TILE_BB
                                  + (uint32_t)((jj * 32 + rr) * 128) + sw;
                CPA16(sa, gB[t] + jj * rstepB + (long long)ck * 128);
            }
        }
        CPA_COMMIT();
    };

    // ---- mma geometry: warps 2(M) x 4(N), warp tile 64x64
    const int mwarp = (wid & 1) * 64, nwarp = (wid >> 1) * 64;
    const int g8 = lane >> 3, id8 = lane & 7;
    const int aRow = ((g8 & 1) << 3) + id8, aC = g8 >> 1;
    const int bRow = (((g8 >> 1) & 1) << 3) + id8, bC = g8 & 1;

    float acc[128];
    #pragma unroll
    for (int i = 0; i < 128; i++) acc[i] = 0.f;

    auto compute_chunk = [&](int stg) {
        const uint32_t s0 = sb + stg * STB;
        const uint32_t at0 = s0, at1 = s0 + TILE_A;
        const uint32_t bt0 = s0 + NPA * TILE_A;
        const uint32_t bt1 = bt0 + TILE_BB;
        #pragma unroll
        for (int kk = 0; kk < 4; kk++) {
            const uint32_t aoff = (uint32_t)(((kk * 2 + aC) ^ id8) << 4);
            const uint32_t boff = (uint32_t)(((kk * 2 + bC) ^ id8) << 4);
            uint32_t a0f[4][4], a1f[4][4], bf[4][4];
            #pragma unroll
            for (int mt = 0; mt < 4; mt++) {
                const uint32_t mrow = (uint32_t)((mwarp + mt * 16 + aRow) * 128);
                LDSM4(a0f[mt][0], a0f[mt][1], a0f[mt][2], a0f[mt][3], at0 + mrow + aoff);
                if (NPA == 2)
                    LDSM4(a1f[mt][0], a1f[mt][1], a1f[mt][2], a1f[mt][3], at1 + mrow + aoff);
            }
            #pragma unroll
            for (int nt = 0; nt < 4; nt++) {
                const uint32_t nrow = (uint32_t)((nwarp + nt * 16 + bRow) * 128);
                LDSM4(bf[nt][0], bf[nt][1], bf[nt][2], bf[nt][3], bt0 + nrow + boff);
            }
            #pragma unroll
            for (int mt = 0; mt < 4; mt++)
                #pragma unroll
                for (int nt = 0; nt < 4; nt++) {
                    MMA_F16(&acc[(mt * 8 + nt * 2) * 4],     a0f[mt], bf[nt][0], bf[nt][1]);
                    MMA_F16(&acc[(mt * 8 + nt * 2 + 1) * 4], a0f[mt], bf[nt][2], bf[nt][3]);
                    if (NPA == 2) {
                        MMA_F16(&acc[(mt * 8 + nt * 2) * 4],     a1f[mt], bf[nt][0], bf[nt][1]);
                        MMA_F16(&acc[(mt * 8 + nt * 2 + 1) * 4], a1f[mt], bf[nt][2], bf[nt][3]);
                    }
                }
            if (NPB == 2) {
                #pragma unroll
                for (int nt = 0; nt < 4; nt++) {
                    const uint32_t nrow = (uint32_t)((nwarp + nt * 16 + bRow) * 128);
                    LDSM4(bf[nt][0], bf[nt][1], bf[nt][2], bf[nt][3], bt1 + nrow + boff);
                }
                #pragma unroll
                for (int mt = 0; mt < 4; mt++)
                    #pragma unroll
                    for (int nt = 0; nt < 4; nt++) {
                        MMA_F16(&acc[(mt * 8 + nt * 2) * 4],     a0f[mt], bf[nt][0], bf[nt][1]);
                        MMA_F16(&acc[(mt * 8 + nt * 2 + 1) * 4], a0f[mt], bf[nt][2], bf[nt][3]);
                    }
            }
        }
    };

    const int nch = Ksub >> 6;
    if constexpr (NSTAGE == 2) {
        load_stage(0, 0);
        for (int i = 0; i < nch; i++) {
            if (i + 1 < nch) { load_stage(i + 1, (i + 1) & 1); CPA_WAIT(1); }
            else             { CPA_WAIT(0); }
            __syncthreads();
            compute_chunk(i & 1);
            __syncthreads();
        }
    } else {
        #pragma unroll
        for (int p = 0; p < NSTAGE - 1; p++) load_stage(p, p);
        for (int i = 0; i < nch; i++) {
            CPA_WAIT(NSTAGE - 2);
            __syncthreads();
            compute_chunk(i % NSTAGE);
            const int nx = i + NSTAGE - 1;
            if (nx < nch) load_stage(nx, nx % NSTAGE);
            else         CPA_COMMIT();
        }
    }

    // ---- epilogue
    const int er = lane >> 2, ec = (lane & 3) * 2;
    const float* e0b = e0 ? (e0 + (long long)bat * se0) : nullptr;
    const float* e3b = e3 ? (e3 + (long long)bat * se3) : nullptr;
    float* Cz = Cf ? (Cf + (long long)z * sC) : nullptr;
    h16* c0z = c0 ? (c0 + (long long)z * sC) : nullptr;
    h16* c1z = c1 ? (c1 + (long long)z * sC) : nullptr;

    #pragma unroll
    for (int mt = 0; mt < 4; mt++) {
        #pragma unroll
        for (int h = 0; h < 2; h++) {
            const int m = by * 128 + mwarp + mt * 16 + er + h * 8;
            float rowadd0 = 0.f, rowadd1 = 0.f, bias = 0.f;
            if (OMODE == 2) { rowadd0 = e0b[m]; rowadd1 = e2[m]; }
            if ((OMODE == 4 || OMODE == 5) && e0) bias = e0b[m];
            #pragma unroll
            for (int nt8 = 0; nt8 < 8; nt8++) {
                const int n = bx * 256 + nwarp + nt8 * 8 + ec;
                float v0 = acc[(mt * 8 + nt8) * 4 + h * 2];
                float v1 = acc[(mt * 8 + nt8) * 4 + h * 2 + 1];
                if (OMODE == 2) {
                    v0 += rowadd0 * e1[n]     + rowadd1 * e3b[n];
                    v1 += rowadd0 * e1[n + 1] + rowadd1 * e3b[n + 1];
                }
                if (OMODE == 0 || OMODE == 2) {
                    *reinterpret_cast<float2*>(Cz + (size_t)m * ldc + n) =
                        make_float2(v0, v1);
                } else if (OMODE == 5) {
                    *reinterpret_cast<__half2*>(c0z + (size_t)m * ldc + n) =
                        __floats2half2_rn(v0 + bias, v1 + bias);
                } else {
                    v0 += bias; v1 += bias;
                    h16 h0a = __float2half(v0);
                    h16 h0b = __float2half(v1);
                    float r0 = v0 - __half2float(h0a);
                    float r1 = v1 - __half2float(h0b);
                    __half2 lo; lo.x = h0a; lo.y = h0b;
                    __half2 hi; hi.x = __float2half(r0); hi.y = __float2half(r1);
                    *reinterpret_cast<__half2*>(c0z + (size_t)m * ldc + n) = lo;
                    *reinterpret_cast<__half2*>(c1z + (size_t)m * ldc + n) = hi;
                }
            }
        }
    }
}

// ---------------- small kernels --------------------------------------------
__device__ __forceinline__ void split_store4(const float4 f, h16* p0, h16* p1, size_t i)
{
    const float v[4] = {f.x, f.y, f.z, f.w};
    __half2 lo[2], hi[2];
    #pragma unroll
    for (int q = 0; q < 2; q++) {
        h16 a0 = __float2half(v[q * 2]);
        h16 a1 = __float2half(v[q * 2 + 1]);
        lo[q].x = a0; lo[q].y = a1;
        hi[q].x = __float2half(v[q * 2]     - __half2float(a0));
        hi[q].y = __float2half(v[q * 2 + 1] - __half2float(a1));
    }
    reinterpret_cast<__half2*>(p0)[i * 2]     = lo[0];
    reinterpret_cast<__half2*>(p0)[i * 2 + 1] = lo[1];
    reinterpret_cast<__half2*>(p1)[i * 2]     = hi[0];
    reinterpret_cast<__half2*>(p1)[i * 2 + 1] = hi[1];
}

// Merged weight split: Wq | Wk | Wv in one launch.
__global__ void wsplit_kernel(const float* __restrict__ Wq, h16* q0, h16* q1,
                              const float* __restrict__ Wk, h16* k0, h16* k1,
                              const float* __restrict__ Wv, h16* v0, h16* v1)
{
    constexpr size_t NQ4 = (size_t)ND * CH / 4;     // 524288
    constexpr size_t NV4 = (size_t)CH * CH / 4;     // 65536
    size_t i = (size_t)blockIdx.x * 256 + threadIdx.x;
    const float* src; h16 *p0, *p1; size_t j;
    if (i < NQ4)            { src = Wq; p0 = q0; p1 = q1; j = i; }
    else if (i < 2 * NQ4)   { src = Wk; p0 = k0; p1 = k1; j = i - NQ4; }
    else                    { src = Wv; p0 = v0; p1 = v1; j = i - 2 * NQ4;
                              if (j >= NV4) return; }
    split_store4(reinterpret_cast<const float4*>(src)[j], p0, p1, j);
}

// x-split with fused rowsum (warps never straddle a 1024-float4 row).
__global__ void split2_rowsum_kernel(const float* __restrict__ src,
                                     h16* __restrict__ p0, h16* __restrict__ p1,
                                     float* __restrict__ s, size_t n4)
{
    size_t i = (size_t)blockIdx.x * 256 + threadIdx.x;
    if (i >= n4) return;
    const float4 f = reinterpret_cast<const float4*>(src)[i];
    split_store4(f, p0, p1, i);
    float partial = (f.x + f.y) + (f.z + f.w);
    #pragma unroll
    for (int o = 16; o; o >>= 1) partial += __shfl_xor_sync(0xffffffffu, partial, o);
    if ((threadIdx.x & 31) == 0)
        atomicAdd(&s[i >> 10], partial);        // row = i / (ND/4)
}

__global__ void zero_kernel(float* __restrict__ p, int n)
{
    int i = blockIdx.x * 256 + threadIdx.x;
    if (i < n) p[i] = 0.f;
}

// Transpose x plane0 (fp16, already rounded) -> xt. Pure fp16 copy-transpose.
__global__ void transpose_kernel(const h16* __restrict__ X0, h16* __restrict__ t0)
{
    __shared__ h16 tile[32][34];
    const int n0 = blockIdx.x * 32, c0 = blockIdx.y * 32, b = blockIdx.z;
    const int tx = threadIdx.x, ty = threadIdx.y;   // 32 x 8
    const h16* Xb = X0 + (size_t)b * CH * ND;
    #pragma unroll
    for (int k = 0; k < 32; k += 8)
        tile[ty + k][tx] = Xb[(size_t)(c0 + ty + k) * ND + n0 + tx];
    __syncthreads();
    h16* d0 = t0 + (size_t)b * ND * CH;
    #pragma unroll
    for (int k = 0; k < 32; k += 8)
        d0[(size_t)(n0 + ty + k) * CH + c0 + tx] = tile[tx][ty + k];
}

__global__ void greduce_split_kernel(const float* __restrict__ Gp,
                                     h16* __restrict__ g0, h16* __restrict__ g1)
{
    const int bat = blockIdx.y;
    const int i = blockIdx.x * 256 + threadIdx.x;      // < 262144
    const float* p = Gp + ((size_t)bat * 8) * 262144 + i;
    float f = 0.f;
    #pragma unroll
    for (int s = 0; s < 8; s++) f += p[(size_t)s * 262144];
    const size_t o = (size_t)bat * 262144 + i;
    h16 a = __float2half(f);
    g0[o] = a;
    g1[o] = __float2half(f - __half2float(a));
}

// Merged gemv: z=0 -> u1 = Wq s + ND*bq ; z=1 -> u2 = Wk s.
__global__ __launch_bounds__(256)
void gemv2_kernel(const float* __restrict__ Wq, const float* __restrict__ bq,
                  const float* __restrict__ Wk,
                  const float* __restrict__ s,
                  float* __restrict__ u1, float* __restrict__ u2)
{
    const int bat = blockIdx.y;
    const int which = blockIdx.z;
    const float* W = which ? Wk : Wq;
    float* y = which ? u2 : u1;
    const int warp = threadIdx.x >> 5, lane = threadIdx.x & 31;
    const int row = blockIdx.x * 8 + warp;
    const float* sv = s + (size_t)bat * CH;
    const float* w = W + (size_t)row * CH;
    float acc = 0.f;
    for (int c = lane; c < CH; c += 32) acc += w[c] * sv[c];
    #pragma unroll
    for (int o = 16; o; o >>= 1) acc += __shfl_xor_sync(0xffffffffu, acc, o);
    if (lane == 0) {
        float b = which ? 0.f : (float)ND * bq[row];
        y[(size_t)bat * ND + row] = acc + b;
    }
}

// softmax over fp32 rows of E; writes P as ONE fp16 plane. float4 loads.
__global__ __launch_bounds__(256)
void softmax_split_kernel(const float* __restrict__ E, h16* __restrict__ p0)
{
    const size_t ro = ((size_t)blockIdx.y * ND + blockIdx.x) * ND;
    const float4* r = reinterpret_cast<const float4*>(E + ro);
    const int tid = threadIdx.x;
    float vals[16];
    float m = -1e30f;
    #pragma unroll
    for (int i = 0; i < 4; i++) {
        const float4 v = r[tid + i * 256];
        vals[i * 4]     = v.x; vals[i * 4 + 1] = v.y;
        vals[i * 4 + 2] = v.z; vals[i * 4 + 3] = v.w;
        m = fmaxf(m, fmaxf(fmaxf(v.x, v.y), fmaxf(v.z, v.w)));
    }
    __shared__ float sh[8];
    #pragma unroll
    for (int o = 16; o; o >>= 1) m = fmaxf(m, __shfl_xor_sync(0xffffffffu, m, o));
    if ((tid & 31) == 0) sh[tid >> 5] = m;
    __syncthreads();
    if (tid < 32) {
        float t = (tid < 8) ? sh[tid] : -1e30f;
        #pragma unroll
        for (int o = 4; o; o >>= 1) t = fmaxf(t, __shfl_xor_sync(0xffffffffu, t, o));
        if (tid == 0) sh[0] = t;
    }
    __syncthreads();
    m = sh[0];
    __syncthreads();
    float s = 0.f;
    #pragma unroll
    for (int i = 0; i < 16; i++) { vals[i] = __expf(vals[i] - m); s += vals[i]; }
    #pragma unroll
    for (int o = 16; o; o >>= 1) s += __shfl_xor_sync(0xffffffffu, s, o);
    if ((tid & 31) == 0) sh[tid >> 5] = s;
    __syncthreads();
    if (tid < 32) {
        float t = (tid < 8) ? sh[tid] : 0.f;
        #pragma unroll
        for (int o = 4; o; o >>= 1) t += __shfl_xor_sync(0xffffffffu, t, o);
        if (tid == 0) sh[0] = t;
    }
    __syncthreads();
    const float inv = 1.0f / sh[0];
    __half2* w0 = reinterpret_cast<__half2*>(p0 + ro);
    #pragma unroll
    for (int i = 0; i < 4; i++) {
        #pragma unroll
        for (int q = 0; q < 2; q++) {
            const int j = (tid + i * 256) * 2 + q;
            w0[j] = __floats2half2_rn(vals[i * 4 + q * 2] * inv,
                                      vals[i * 4 + q * 2 + 1] * inv);
        }
    }
}

// ---------------------------------------------------------------------------
extern "C" void kernel_launch(void* const* d_in, const int* in_sizes, int n_in,
                              void* d_out, int out_size)
{
    const float* x  = (const float*)d_in[0];
    const float* Wq = (const float*)d_in[1];
    const float* bq = (const float*)d_in[2];
    const float* Wk = (const float*)d_in[3];
    const float* bk = (const float*)d_in[4];
    const float* Wv = (const float*)d_in[5];
    const float* bv = (const float*)d_in[6];
    float* out = (float*)d_out;

    h16 *x0, *xt0, *wq0, *wk0, *wv0, *gg0, *kh0, *vv0, *pp0;
    float *E, *Gp, *s, *u1, *u2;
    cudaGetSymbolAddress((void**)&x0,  g_x);
    cudaGetSymbolAddress((void**)&xt0, g_xt);
    cudaGetSymbolAddress((void**)&wq0, g_wq);
    cudaGetSymbolAddress((void**)&wk0, g_wk);
    cudaGetSymbolAddress((void**)&wv0, g_wv);
    cudaGetSymbolAddress((void**)&gg0, g_gg);
    cudaGetSymbolAddress((void**)&kh0, g_kh);
    cudaGetSymbolAddress((void**)&vv0, g_vv);
    cudaGetSymbolAddress((void**)&pp0, g_pp);
    cudaGetSymbolAddress((void**)&E,  g_E);
    cudaGetSymbolAddress((void**)&Gp, g_Gp);
    cudaGetSymbolAddress((void**)&s,  g_s);
    cudaGetSymbolAddress((void**)&u1, g_u1);
    cudaGetSymbolAddress((void**)&u2, g_u2);

    const size_t PX = (size_t)NB * CH * ND;
    const size_t PW = (size_t)ND * CH;
    const size_t PV = (size_t)CH * CH;
    const size_t PG = (size_t)NB * CH * CH;
    const size_t PK = (size_t)NB * ND * CH;
    h16 *x1 = x0 + PX;
    h16 *wq1 = wq0 + PW, *wk1 = wk0 + PW, *wv1 = wv0 + PV;
    h16 *gg1 = gg0 + PG, *kh1 = kh0 + PK;

    const int SMEM = 196608;
    cudaFuncSetAttribute(tc_gemm<2,2,2,0>, cudaFuncAttributeMaxDynamicSharedMemorySize, SMEM);
    cudaFuncSetAttribute(tc_gemm<2,2,2,2>, cudaFuncAttributeMaxDynamicSharedMemorySize, SMEM);
    cudaFuncSetAttribute(tc_gemm<2,2,2,4>, cudaFuncAttributeMaxDynamicSharedMemorySize, SMEM);
    cudaFuncSetAttribute(tc_gemm<2,1,3,5>, cudaFuncAttributeMaxDynamicSharedMemorySize, SMEM);
    cudaFuncSetAttribute(tc_gemm<1,1,4,0>, cudaFuncAttributeMaxDynamicSharedMemorySize, SMEM);

    // prologue: s = 0; x split (+rowsum); transpose(fp16); weight splits; gemvs
    zero_kernel<<<8, 256>>>(s, NB * CH);
    split2_rowsum_kernel<<<(unsigned)(PX / 4 / 256), 256>>>(x, x0, x1, s, PX / 4);
    transpose_kernel<<<dim3(128, 16, NB), dim3(32, 8)>>>(x0, xt0);
    wsplit_kernel<<<(unsigned)((2 * PW / 4 + PV / 4 + 255) / 256), 256>>>(
        Wq, wq0, wq1, Wk, wk0, wk1, Wv, wv0, wv1);
    gemv2_kernel<<<dim3(ND / 8, NB, 2), 256>>>(Wq, bq, Wk, s, u1, u2);

    const long long sX = (long long)CH * ND;
    const long long sG = (long long)CH * CH;
    const long long sK = (long long)ND * CH;
    const long long sE = (long long)ND * ND;

    // G_b = X X^T  (split-K 8, fp32 partials), then reduce + split
    tc_gemm<2,2,2,0><<<dim3(2, 4, 32), 256, SMEM>>>(
        x0, x1, x0, x1, 512, 8, ND, ND, sX, sX,
        Gp, nullptr, nullptr, CH, sG,
        nullptr, 0, nullptr, nullptr, nullptr, 0);
    greduce_split_kernel<<<dim3(1024, NB), 256>>>(Gp, gg0, gg1);

    // Khat_b = Wk G_b  (G symmetric -> NT), split2 output
    tc_gemm<2,2,2,4><<<dim3(2, 32, NB), 256, SMEM>>>(
        wk0, wk1, gg0, gg1, CH, 1, CH, CH, 0, sG,
        nullptr, kh0, kh1, CH, sK,
        nullptr, 0, nullptr, nullptr, nullptr, 0);

    // V_b = Wv X_b + bv  (B = xt single plane), 2 products, 3-stage
    tc_gemm<2,1,3,5><<<dim3(16, 4, NB), 256, SMEM>>>(
        wv0, wv1, xt0, nullptr, CH, 1, CH, CH, 0, sK,
        nullptr, vv0, nullptr, ND, sX,
        bv, 0, nullptr, nullptr, nullptr, 0);

    // E + softmax in 2 rounds of 2 batches: E stays L2-hot for the softmax
    // read. Wave-neutral for E (1024 CTAs/round = 7 waves, x2 = 14 = batched).
    for (int rnd = 0; rnd < 2; rnd++) {
        const long long bo = 2LL * rnd;
        tc_gemm<2,2,2,2><<<dim3(16, 32, 2), 256, SMEM>>>(
            wq0, wq1, kh0 + bo * sK, kh1 + bo * sK, CH, 1, CH, CH, 0, sK,
            E + bo * sE, nullptr, nullptr, ND, sE,
            u1 + bo * ND, ND, bk, bq, u2 + bo * ND, ND);
        softmax_split_kernel<<<dim3(ND, 2), 256>>>(E + bo * sE, pp0 + bo * sE);
    }

    // out_b = V_b P_b^T, 1 product, 4-stage, fp32
    tc_gemm<1,1,4,0><<<dim3(16, 4, NB), 256, SMEM>>>(
        vv0, nullptr, pp0, nullptr, ND, 1, ND, ND, sX, sE,
        out, nullptr, nullptr, ND, sX,
        nullptr, 0, nullptr, nullptr, nullptr, 0);
}

// round 14
// speedup vs baseline: 1.0040x; 1.0040x over previous
#include <cuda_runtime.h>
#include <cuda_fp16.h>
#include <cstdint>
#include <cstddef>

// ===========================================================================
// HyperNodeAggregation via mma.sync fp16 multi-product GEMMs (fp32 accum).
//   E_b = Wq (Wk G_b)^T + u1 bk^T + bq u2^T,  G_b = X X^T (symmetric)
//   P = softmax(E);  V = Wv X + bv 1^T;  out = V P^T
// fp32 operands split into 2 fp16 planes (residual 2^-11).
// Products: logit chain (G, Khat, E) = 3;  V = 2;  out = 1.
// R14: revert R13's E/softmax chaining (L2 theory disproven); keep fp16
//      transpose; wsplit 2x float4 per thread.
// ===========================================================================

using h16 = __half;

constexpr int NB = 4, CH = 512, ND = 4096;

// ---------------- scratch (device globals; allocation-free rule) -----------
__device__ __align__(128) h16 g_x [2][(size_t)NB * CH * ND];
__device__ __align__(128) h16 g_xt[(size_t)NB * ND * CH];      // single plane
__device__ __align__(128) h16 g_wq[2][(size_t)ND * CH];
__device__ __align__(128) h16 g_wk[2][(size_t)ND * CH];
__device__ __align__(128) h16 g_wv[2][(size_t)CH * CH];
__device__ __align__(128) h16 g_gg[2][(size_t)NB * CH * CH];
__device__ __align__(128) h16 g_kh[2][(size_t)NB * ND * CH];
__device__ __align__(128) h16 g_vv[(size_t)NB * CH * ND];      // single plane
__device__ __align__(128) h16 g_pp[(size_t)NB * ND * ND];      // single plane
__device__ __align__(128) float g_E [(size_t)NB * ND * ND];
__device__ __align__(128) float g_Gp[(size_t)32 * CH * CH];
__device__ float g_s[NB * CH], g_u1[NB * ND], g_u2[NB * ND];

// ---------------- asm helpers ----------------------------------------------
__device__ __forceinline__ uint32_t smem_to_u32(const void* p) {
    uint32_t a;
    asm("{ .reg .u64 t; cvta.to.shared.u64 t, %1; cvt.u32.u64 %0, t; }"
        : "=r"(a) : "l"(p));
    return a;
}
#define CPA16(s, g) \
    asm volatile("cp.async.cg.shared.global [%0], [%1], 16;" :: "r"(s), "l"(g) : "memory")
#define CPA_COMMIT() asm volatile("cp.async.commit_group;" ::: "memory")
#define CPA_WAIT(n)  asm volatile("cp.async.wait_group %0;" :: "n"(n) : "memory")
#define LDSM4(r0, r1, r2, r3, addr) \
    asm volatile("ldmatrix.sync.aligned.m8n8.x4.shared.b16 {%0,%1,%2,%3}, [%4];" \
        : "=r"(r0), "=r"(r1), "=r"(r2), "=r"(r3) : "r"(addr))
#define MMA_F16(d, a, bb0, bb1) \
    asm volatile("mma.sync.aligned.m16n8k16.row.col.f32.f16.f16.f32 " \
        "{%0,%1,%2,%3}, {%4,%5,%6,%7}, {%8,%9}, {%0,%1,%2,%3};" \
        : "+f"((d)[0]), "+f"((d)[1]), "+f"((d)[2]), "+f"((d)[3]) \
        : "r"((a)[0]), "r"((a)[1]), "r"((a)[2]), "r"((a)[3]), "r"(bb0), "r"(bb1))

// ===========================================================================
// tc_gemm<NPA, NPB, NSTAGE, OMODE>: C[128x256/CTA], NT GEMM, K-contig.
// Products: a0.b0  (+ a1.b0 if NPA==2)  (+ a0.b1 if NPB==2).
// BK=64 (128B rows, swizzle chunk ^= row&7). NSTAGE-deep cp.async pipeline;
// NSTAGE>=3 uses a single __syncthreads per chunk.
// 8 warps as 2(M) x 4(N); warp tile 64x64; m16n8k16 f16 mma, fp32 accum.
// OMODE: 0 fp32; 2 fp32 + rank-2 e0[m]e1[n]+e2[m]e3[n];
//        4 2-plane fp16 split store (+bias e0[m]); 5 1-plane fp16 (+bias).
// Split-K via nsplit. Requires nch >= NSTAGE-1.
// ===========================================================================
#define TILE_A  16384           // 128 rows * 128 B
#define TILE_BB 32768           // 256 rows * 128 B

template<int NPA, int NPB, int NSTAGE, int OMODE>
__global__ void __launch_bounds__(256, 1)
tc_gemm(const h16* __restrict__ a0, const h16* __restrict__ a1,
        const h16* __restrict__ b0, const h16* __restrict__ b1,
        int Ksub, int nsplit, int lda, int ldb, long long sA, long long sB,
        float* __restrict__ Cf, h16* __restrict__ c0, h16* __restrict__ c1,
        int ldc, long long sC,
        const float* __restrict__ e0, long long se0,
        const float* __restrict__ e1, const float* __restrict__ e2,
        const float* __restrict__ e3, long long se3)
{
    constexpr int STB = NPA * TILE_A + NPB * TILE_BB;   // stage bytes
    extern __shared__ __align__(1024) char smem[];
    const uint32_t sb = smem_to_u32(smem);
    const int tid = threadIdx.x, wid = tid >> 5, lane = tid & 31;
    const int bx = blockIdx.x, by = blockIdx.y, z = blockIdx.z;
    const int bat = z / nsplit, sp = z - bat * nsplit;

    // ---- cp.async geometry
    const int rr = tid >> 3;                 // 0..31
    const int qq = tid & 7;                  // 0..7
    const uint32_t sw = (uint32_t)((qq ^ (rr & 7)) << 4);
    const long long koffB = (long long)sp * Ksub * 2;

    const char* gA[2];
    const char* gB[2];
    long long rstepA, rstepB;
    {
        const long long la2 = (long long)lda * 2, lb2 = (long long)ldb * 2;
        gA[0] = (const char*)(a0 + (long long)bat * sA)
              + (long long)(by * 128) * la2 + rr * la2 + qq * 16 + koffB;
        gA[1] = (NPA == 2)
              ? (const char*)(a1 + (long long)bat * sA)
                + (long long)(by * 128) * la2 + rr * la2 + qq * 16 + koffB
              : nullptr;
        gB[0] = (const char*)(b0 + (long long)bat * sB)
              + (long long)(bx * 256) * lb2 + rr * lb2 + qq * 16 + koffB;
        gB[1] = (NPB == 2)
              ? (const char*)(b1 + (long long)bat * sB)
                + (long long)(bx * 256) * lb2 + rr * lb2 + qq * 16 + koffB
              : nullptr;
        rstepA = la2 * 32;
        rstepB = lb2 * 32;
    }

    auto load_stage = [&](int ck, int stg) {
        const uint32_t s0 = sb + stg * STB;
        #pragma unroll
        for (int t = 0; t < NPA; t++) {
            #pragma unroll
            for (int jj = 0; jj < 4; jj++) {       // A: 128 rows
                const uint32_t sa = s0 + t * TILE_A
                                  + (uint32_t)((jj * 32 + rr) * 128) + sw;
                CPA16(sa, gA[t] + jj * rstepA + (long long)ck * 128);
            }
        }
        #pragma unroll
        for (int t = 0; t < NPB; t++) {
            #pragma unroll
            for (int jj = 0; jj < 8; jj++) {       // B: 256 rows
                const uint32_t sa = s0 + NPA * TILE_A + t * TILE_BB
                                  + (uint32_t)((jj * 32 + rr) * 128) + sw;
                CPA16(sa, gB[t] + jj * rstepB + (long long)ck * 128);
            }
        }
        CPA_COMMIT();
    };

    // ---- mma geometry: warps 2(M) x 4(N), warp tile 64x64
    const int mwarp = (wid & 1) * 64, nwarp = (wid >> 1) * 64;
    const int g8 = lane >> 3, id8 = lane & 7;
    const int aRow = ((g8 & 1) << 3) + id8, aC = g8 >> 1;
    const int bRow = (((g8 >> 1) & 1) << 3) + id8, bC = g8 & 1;

    float acc[128];
    #pragma unroll
    for (int i = 0; i < 128; i++) acc[i] = 0.f;

    auto compute_chunk = [&](int stg) {
        const uint32_t s0 = sb + stg * STB;
        const uint32_t at0 = s0, at1 = s0 + TILE_A;
        const uint32_t bt0 = s0 + NPA * TILE_A;
        const uint32_t bt1 = bt0 + TILE_BB;
        #pragma unroll
        for (int kk = 0; kk < 4; kk++) {
            const uint32_t aoff = (uint32_t)(((kk * 2 + aC) ^ id8) << 4);
            const uint32_t boff = (uint32_t)(((kk * 2 + bC) ^ id8) << 4);
            uint32_t a0f[4][4], a1f[4][4], bf[4][4];
            #pragma unroll
            for (int mt = 0; mt < 4; mt++) {
                const uint32_t mrow = (uint32_t)((mwarp + mt * 16 + aRow) * 128);
                LDSM4(a0f[mt][0], a0f[mt][1], a0f[mt][2], a0f[mt][3], at0 + mrow + aoff);
                if (NPA == 2)
                    LDSM4(a1f[mt][0], a1f[mt][1], a1f[mt][2], a1f[mt][3], at1 + mrow + aoff);
            }
            #pragma unroll
            for (int nt = 0; nt < 4; nt++) {
                const uint32_t nrow = (uint32_t)((nwarp + nt * 16 + bRow) * 128);
                LDSM4(bf[nt][0], bf[nt][1], bf[nt][2], bf[nt][3], bt0 + nrow + boff);
            }
            #pragma unroll
            for (int mt = 0; mt < 4; mt++)
                #pragma unroll
                for (int nt = 0; nt < 4; nt++) {
                    MMA_F16(&acc[(mt * 8 + nt * 2) * 4],     a0f[mt], bf[nt][0], bf[nt][1]);
                    MMA_F16(&acc[(mt * 8 + nt * 2 + 1) * 4], a0f[mt], bf[nt][2], bf[nt][3]);
                    if (NPA == 2) {
                        MMA_F16(&acc[(mt * 8 + nt * 2) * 4],     a1f[mt], bf[nt][0], bf[nt][1]);
                        MMA_F16(&acc[(mt * 8 + nt * 2 + 1) * 4], a1f[mt], bf[nt][2], bf[nt][3]);
                    }
                }
            if (NPB == 2) {
                #pragma unroll
                for (int nt = 0; nt < 4; nt++) {
                    const uint32_t nrow = (uint32_t)((nwarp + nt * 16 + bRow) * 128);
                    LDSM4(bf[nt][0], bf[nt][1], bf[nt][2], bf[nt][3], bt1 + nrow + boff);
                }
                #pragma unroll
                for (int mt = 0; mt < 4; mt++)
                    #pragma unroll
                    for (int nt = 0; nt < 4; nt++) {
                        MMA_F16(&acc[(mt * 8 + nt * 2) * 4],     a0f[mt], bf[nt][0], bf[nt][1]);
                        MMA_F16(&acc[(mt * 8 + nt * 2 + 1) * 4], a0f[mt], bf[nt][2], bf[nt][3]);
                    }
            }
        }
    };

    const int nch = Ksub >> 6;
    if constexpr (NSTAGE == 2) {
        load_stage(0, 0);
        for (int i = 0; i < nch; i++) {
            if (i + 1 < nch) { load_stage(i + 1, (i + 1) & 1); CPA_WAIT(1); }
            else             { CPA_WAIT(0); }
            __syncthreads();
            compute_chunk(i & 1);
            __syncthreads();
        }
    } else {
        #pragma unroll
        for (int p = 0; p < NSTAGE - 1; p++) load_stage(p, p);
        for (int i = 0; i < nch; i++) {
            CPA_WAIT(NSTAGE - 2);
            __syncthreads();
            compute_chunk(i % NSTAGE);
            const int nx = i + NSTAGE - 1;
            if (nx < nch) load_stage(nx, nx % NSTAGE);
            else         CPA_COMMIT();
        }
    }

    // ---- epilogue
    const int er = lane >> 2, ec = (lane & 3) * 2;
    const float* e0b = e0 ? (e0 + (long long)bat * se0) : nullptr;
    const float* e3b = e3 ? (e3 + (long long)bat * se3) : nullptr;
    float* Cz = Cf ? (Cf + (long long)z * sC) : nullptr;
    h16* c0z = c0 ? (c0 + (long long)z * sC) : nullptr;
    h16* c1z = c1 ? (c1 + (long long)z * sC) : nullptr;

    #pragma unroll
    for (int mt = 0; mt < 4; mt++) {
        #pragma unroll
        for (int h = 0; h < 2; h++) {
            const int m = by * 128 + mwarp + mt * 16 + er + h * 8;
            float rowadd0 = 0.f, rowadd1 = 0.f, bias = 0.f;
            if (OMODE == 2) { rowadd0 = e0b[m]; rowadd1 = e2[m]; }
            if ((OMODE == 4 || OMODE == 5) && e0) bias = e0b[m];
            #pragma unroll
            for (int nt8 = 0; nt8 < 8; nt8++) {
                const int n = bx * 256 + nwarp + nt8 * 8 + ec;
                float v0 = acc[(mt * 8 + nt8) * 4 + h * 2];
                float v1 = acc[(mt * 8 + nt8) * 4 + h * 2 + 1];
                if (OMODE == 2) {
                    v0 += rowadd0 * e1[n]     + rowadd1 * e3b[n];
                    v1 += rowadd0 * e1[n + 1] + rowadd1 * e3b[n + 1];
                }
                if (OMODE == 0 || OMODE == 2) {
                    *reinterpret_cast<float2*>(Cz + (size_t)m * ldc + n) =
                        make_float2(v0, v1);
                } else if (OMODE == 5) {
                    *reinterpret_cast<__half2*>(c0z + (size_t)m * ldc + n) =
                        __floats2half2_rn(v0 + bias, v1 + bias);
                } else {
                    v0 += bias; v1 += bias;
                    h16 h0a = __float2half(v0);
                    h16 h0b = __float2half(v1);
                    float r0 = v0 - __half2float(h0a);
                    float r1 = v1 - __half2float(h0b);
                    __half2 lo; lo.x = h0a; lo.y = h0b;
                    __half2 hi; hi.x = __float2half(r0); hi.y = __float2half(r1);
                    *reinterpret_cast<__half2*>(c0z + (size_t)m * ldc + n) = lo;
                    *reinterpret_cast<__half2*>(c1z + (size_t)m * ldc + n) = hi;
                }
            }
        }
    }
}

// ---------------- small kernels --------------------------------------------
__device__ __forceinline__ void split_store4(const float4 f, h16* p0, h16* p1, size_t i)
{
    const float v[4] = {f.x, f.y, f.z, f.w};
    __half2 lo[2], hi[2];
    #pragma unroll
    for (int q = 0; q < 2; q++) {
        h16 a0 = __float2half(v[q * 2]);
        h16 a1 = __float2half(v[q * 2 + 1]);
        lo[q].x = a0; lo[q].y = a1;
        hi[q].x = __float2half(v[q * 2]     - __half2float(a0));
        hi[q].y = __float2half(v[q * 2 + 1] - __half2float(a1));
    }
    reinterpret_cast<__half2*>(p0)[i * 2]     = lo[0];
    reinterpret_cast<__half2*>(p0)[i * 2 + 1] = lo[1];
    reinterpret_cast<__half2*>(p1)[i * 2]     = hi[0];
    reinterpret_cast<__half2*>(p1)[i * 2 + 1] = hi[1];
}

// Merged weight split: Wq | Wk | Wv, 2 float4 per thread.
__global__ void wsplit_kernel(const float* __restrict__ Wq, h16* q0, h16* q1,
                              const float* __restrict__ Wk, h16* k0, h16* k1,
                              const float* __restrict__ Wv, h16* v0, h16* v1)
{
    constexpr size_t NQ4 = (size_t)ND * CH / 4;     // 524288
    constexpr size_t NV4 = (size_t)CH * CH / 4;     // 65536
    const size_t base = ((size_t)blockIdx.x * 256 + threadIdx.x) * 2;
    #pragma unroll
    for (int u = 0; u < 2; u++) {
        const size_t i = base + u;
        const float* src; h16 *p0, *p1; size_t j;
        if (i < NQ4)            { src = Wq; p0 = q0; p1 = q1; j = i; }
        else if (i < 2 * NQ4)   { src = Wk; p0 = k0; p1 = k1; j = i - NQ4; }
        else                    { src = Wv; p0 = v0; p1 = v1; j = i - 2 * NQ4;
                                  if (j >= NV4) continue; }
        split_store4(reinterpret_cast<const float4*>(src)[j], p0, p1, j);
    }
}

// x-split with fused rowsum (warps never straddle a 1024-float4 row).
__global__ void split2_rowsum_kernel(const float* __restrict__ src,
                                     h16* __restrict__ p0, h16* __restrict__ p1,
                                     float* __restrict__ s, size_t n4)
{
    size_t i = (size_t)blockIdx.x * 256 + threadIdx.x;
    if (i >= n4) return;
    const float4 f = reinterpret_cast<const float4*>(src)[i];
    split_store4(f, p0, p1, i);
    float partial = (f.x + f.y) + (f.z + f.w);
    #pragma unroll
    for (int o = 16; o; o >>= 1) partial += __shfl_xor_sync(0xffffffffu, partial, o);
    if ((threadIdx.x & 31) == 0)
        atomicAdd(&s[i >> 10], partial);        // row = i / (ND/4)
}

__global__ void zero_kernel(float* __restrict__ p, int n)
{
    int i = blockIdx.x * 256 + threadIdx.x;
    if (i < n) p[i] = 0.f;
}

// Transpose x plane0 (fp16, already rounded) -> xt. Pure fp16 copy-transpose.
__global__ void transpose_kernel(const h16* __restrict__ X0, h16* __restrict__ t0)
{
    __shared__ h16 tile[32][34];
    const int n0 = blockIdx.x * 32, c0 = blockIdx.y * 32, b = blockIdx.z;
    const int tx = threadIdx.x, ty = threadIdx.y;   // 32 x 8
    const h16* Xb = X0 + (size_t)b * CH * ND;
    #pragma unroll
    for (int k = 0; k < 32; k += 8)
        tile[ty + k][tx] = Xb[(size_t)(c0 + ty + k) * ND + n0 + tx];
    __syncthreads();
    h16* d0 = t0 + (size_t)b * ND * CH;
    #pragma unroll
    for (int k = 0; k < 32; k += 8)
        d0[(size_t)(n0 + ty + k) * CH + c0 + tx] = tile[tx][ty + k];
}

__global__ void greduce_split_kernel(const float* __restrict__ Gp,
                                     h16* __restrict__ g0, h16* __restrict__ g1)
{
    const int bat = blockIdx.y;
    const int i = blockIdx.x * 256 + threadIdx.x;      // < 262144
    const float* p = Gp + ((size_t)bat * 8) * 262144 + i;
    float f = 0.f;
    #pragma unroll
    for (int s = 0; s < 8; s++) f += p[(size_t)s * 262144];
    const size_t o = (size_t)bat * 262144 + i;
    h16 a = __float2half(f);
    g0[o] = a;
    g1[o] = __float2half(f - __half2float(a));
}

// Merged gemv: z=0 -> u1 = Wq s + ND*bq ; z=1 -> u2 = Wk s.
__global__ __launch_bounds__(256)
void gemv2_kernel(const float* __restrict__ Wq, const float* __restrict__ bq,
                  const float* __restrict__ Wk,
                  const float* __restrict__ s,
                  float* __restrict__ u1, float* __restrict__ u2)
{
    const int bat = blockIdx.y;
    const int which = blockIdx.z;
    const float* W = which ? Wk : Wq;
    float* y = which ? u2 : u1;
    const int warp = threadIdx.x >> 5, lane = threadIdx.x & 31;
    const int row = blockIdx.x * 8 + warp;
    const float* sv = s + (size_t)bat * CH;
    const float* w = W + (size_t)row * CH;
    float acc = 0.f;
    for (int c = lane; c < CH; c += 32) acc += w[c] * sv[c];
    #pragma unroll
    for (int o = 16; o; o >>= 1) acc += __shfl_xor_sync(0xffffffffu, acc, o);
    if (lane == 0) {
        float b = which ? 0.f : (float)ND * bq[row];
        y[(size_t)bat * ND + row] = acc + b;
    }
}

// softmax over fp32 rows of E; writes P as ONE fp16 plane. float4 loads.
__global__ __launch_bounds__(256)
void softmax_split_kernel(const float* __restrict__ E, h16* __restrict__ p0)
{
    const size_t ro = ((size_t)blockIdx.y * ND + blockIdx.x) * ND;
    const float4* r = reinterpret_cast<const float4*>(E + ro);
    const int tid = threadIdx.x;
    float vals[16];
    float m = -1e30f;
    #pragma unroll
    for (int i = 0; i < 4; i++) {
        const float4 v = r[tid + i * 256];
        vals[i * 4]     = v.x; vals[i * 4 + 1] = v.y;
        vals[i * 4 + 2] = v.z; vals[i * 4 + 3] = v.w;
        m = fmaxf(m, fmaxf(fmaxf(v.x, v.y), fmaxf(v.z, v.w)));
    }
    __shared__ float sh[8];
    #pragma unroll
    for (int o = 16; o; o >>= 1) m = fmaxf(m, __shfl_xor_sync(0xffffffffu, m, o));
    if ((tid & 31) == 0) sh[tid >> 5] = m;
    __syncthreads();
    if (tid < 32) {
        float t = (tid < 8) ? sh[tid] : -1e30f;
        #pragma unroll
        for (int o = 4; o; o >>= 1) t = fmaxf(t, __shfl_xor_sync(0xffffffffu, t, o));
        if (tid == 0) sh[0] = t;
    }
    __syncthreads();
    m = sh[0];
    __syncthreads();
    float s = 0.f;
    #pragma unroll
    for (int i = 0; i < 16; i++) { vals[i] = __expf(vals[i] - m); s += vals[i]; }
    #pragma unroll
    for (int o = 16; o; o >>= 1) s += __shfl_xor_sync(0xffffffffu, s, o);
    if ((tid & 31) == 0) sh[tid >> 5] = s;
    __syncthreads();
    if (tid < 32) {
        float t = (tid < 8) ? sh[tid] : 0.f;
        #pragma unroll
        for (int o = 4; o; o >>= 1) t += __shfl_xor_sync(0xffffffffu, t, o);
        if (tid == 0) sh[0] = t;
    }
    __syncthreads();
    const float inv = 1.0f / sh[0];
    __half2* w0 = reinterpret_cast<__half2*>(p0 + ro);
    #pragma unroll
    for (int i = 0; i < 4; i++) {
        #pragma unroll
        for (int q = 0; q < 2; q++) {
            const int j = (tid + i * 256) * 2 + q;
            w0[j] = __floats2half2_rn(vals[i * 4 + q * 2] * inv,
                                      vals[i * 4 + q * 2 + 1] * inv);
        }
    }
}

// ---------------------------------------------------------------------------
extern "C" void kernel_launch(void* const* d_in, const int* in_sizes, int n_in,
                              void* d_out, int out_size)
{
    const float* x  = (const float*)d_in[0];
    const float* Wq = (const float*)d_in[1];
    const float* bq = (const float*)d_in[2];
    const float* Wk = (const float*)d_in[3];
    const float* bk = (const float*)d_in[4];
    const float* Wv = (const float*)d_in[5];
    const float* bv = (const float*)d_in[6];
    float* out = (float*)d_out;

    h16 *x0, *xt0, *wq0, *wk0, *wv0, *gg0, *kh0, *vv0, *pp0;
    float *E, *Gp, *s, *u1, *u2;
    cudaGetSymbolAddress((void**)&x0,  g_x);
    cudaGetSymbolAddress((void**)&xt0, g_xt);
    cudaGetSymbolAddress((void**)&wq0, g_wq);
    cudaGetSymbolAddress((void**)&wk0, g_wk);
    cudaGetSymbolAddress((void**)&wv0, g_wv);
    cudaGetSymbolAddress((void**)&gg0, g_gg);
    cudaGetSymbolAddress((void**)&kh0, g_kh);
    cudaGetSymbolAddress((void**)&vv0, g_vv);
    cudaGetSymbolAddress((void**)&pp0, g_pp);
    cudaGetSymbolAddress((void**)&E,  g_E);
    cudaGetSymbolAddress((void**)&Gp, g_Gp);
    cudaGetSymbolAddress((void**)&s,  g_s);
    cudaGetSymbolAddress((void**)&u1, g_u1);
    cudaGetSymbolAddress((void**)&u2, g_u2);

    const size_t PX = (size_t)NB * CH * ND;
    const size_t PW = (size_t)ND * CH;
    const size_t PV = (size_t)CH * CH;
    const size_t PG = (size_t)NB * CH * CH;
    const size_t PK = (size_t)NB * ND * CH;
    h16 *x1 = x0 + PX;
    h16 *wq1 = wq0 + PW, *wk1 = wk0 + PW, *wv1 = wv0 + PV;
    h16 *gg1 = gg0 + PG, *kh1 = kh0 + PK;

    const int SMEM = 196608;
    cudaFuncSetAttribute(tc_gemm<2,2,2,0>, cudaFuncAttributeMaxDynamicSharedMemorySize, SMEM);
    cudaFuncSetAttribute(tc_gemm<2,2,2,2>, cudaFuncAttributeMaxDynamicSharedMemorySize, SMEM);
    cudaFuncSetAttribute(tc_gemm<2,2,2,4>, cudaFuncAttributeMaxDynamicSharedMemorySize, SMEM);
    cudaFuncSetAttribute(tc_gemm<2,1,3,5>, cudaFuncAttributeMaxDynamicSharedMemorySize, SMEM);
    cudaFuncSetAttribute(tc_gemm<1,1,4,0>, cudaFuncAttributeMaxDynamicSharedMemorySize, SMEM);

    // prologue: s = 0; x split (+rowsum); transpose(fp16); weight splits; gemvs
    zero_kernel<<<8, 256>>>(s, NB * CH);
    split2_rowsum_kernel<<<(unsigned)(PX / 4 / 256), 256>>>(x, x0, x1, s, PX / 4);
    transpose_kernel<<<dim3(128, 16, NB), dim3(32, 8)>>>(x0, xt0);
    wsplit_kernel<<<(unsigned)((2 * PW / 4 + PV / 4 + 511) / 512), 256>>>(
        Wq, wq0, wq1, Wk, wk0, wk1, Wv, wv0, wv1);
    gemv2_kernel<<<dim3(ND / 8, NB, 2), 256>>>(Wq, bq, Wk, s, u1, u2);

    const long long sX = (long long)CH * ND;
    const long long sG = (long long)CH * CH;
    const long long sK = (long long)ND * CH;
    const long long sE = (long long)ND * ND;

    // G_b = X X^T  (split-K 8, fp32 partials), then reduce + split
    tc_gemm<2,2,2,0><<<dim3(2, 4, 32), 256, SMEM>>>(
        x0, x1, x0, x1, 512, 8, ND, ND, sX, sX,
        Gp, nullptr, nullptr, CH, sG,
        nullptr, 0, nullptr, nullptr, nullptr, 0);
    greduce_split_kernel<<<dim3(1024, NB), 256>>>(Gp, gg0, gg1);

    // Khat_b = Wk G_b  (G symmetric -> NT), split2 output
    tc_gemm<2,2,2,4><<<dim3(2, 32, NB), 256, SMEM>>>(
        wk0, wk1, gg0, gg1, CH, 1, CH, CH, 0, sG,
        nullptr, kh0, kh1, CH, sK,
        nullptr, 0, nullptr, nullptr, nullptr, 0);

    // V_b = Wv X_b + bv  (B = xt single plane), 2 products, 3-stage
    tc_gemm<2,1,3,5><<<dim3(16, 4, NB), 256, SMEM>>>(
        wv0, wv1, xt0, nullptr, CH, 1, CH, CH, 0, sK,
        nullptr, vv0, nullptr, ND, sX,
        bv, 0, nullptr, nullptr, nullptr, 0);

    // E_b = Wq Khat^T + u1 bk^T + bq u2^T, fp32 + rank-2 (batched)
    tc_gemm<2,2,2,2><<<dim3(16, 32, NB), 256, SMEM>>>(
        wq0, wq1, kh0, kh1, CH, 1, CH, CH, 0, sK,
        E, nullptr, nullptr, ND, sE,
        u1, ND, bk, bq, u2, ND);

    // P = softmax(E) -> ONE fp16 plane (batched)
    softmax_split_kernel<<<dim3(ND, NB), 256>>>(E, pp0);

    // out_b = V_b P_b^T, 1 product, 4-stage, fp32
    tc_gemm<1,1,4,0><<<dim3(16, 4, NB), 256, SMEM>>>(
        vv0, nullptr, pp0, nullptr, ND, 1, ND, ND, sX, sE,
        out, nullptr, nullptr, ND, sX,
        nullptr, 0, nullptr, nullptr, nullptr, 0);
}

// round 15
// speedup vs baseline: 1.0055x; 1.0015x over previous
#include <cuda_runtime.h>
#include <cuda_fp16.h>
#include <cstdint>
#include <cstddef>

// ===========================================================================
// HyperNodeAggregation via mma.sync fp16 multi-product GEMMs (fp32 accum).
//   E_b = Wq (Wk G_b)^T + u1 bk^T + bq u2^T,  G_b = X X^T (symmetric)
//   P = softmax(E);  V = Wv X + bv 1^T;  out = V P^T
// fp32 operands split into 2 fp16 planes (residual 2^-11).
// Products: logit chain (G, Khat, E) = 3;  V = 2;  out = 1.
// R15: best-known component set (R12 wsplit restored; fp16 transpose kept).
// ===========================================================================

using h16 = __half;

constexpr int NB = 4, CH = 512, ND = 4096;

// ---------------- scratch (device globals; allocation-free rule) -----------
__device__ __align__(128) h16 g_x [2][(size_t)NB * CH * ND];
__device__ __align__(128) h16 g_xt[(size_t)NB * ND * CH];      // single plane
__device__ __align__(128) h16 g_wq[2][(size_t)ND * CH];
__device__ __align__(128) h16 g_wk[2][(size_t)ND * CH];
__device__ __align__(128) h16 g_wv[2][(size_t)CH * CH];
__device__ __align__(128) h16 g_gg[2][(size_t)NB * CH * CH];
__device__ __align__(128) h16 g_kh[2][(size_t)NB * ND * CH];
__device__ __align__(128) h16 g_vv[(size_t)NB * CH * ND];      // single plane
__device__ __align__(128) h16 g_pp[(size_t)NB * ND * ND];      // single plane
__device__ __align__(128) float g_E [(size_t)NB * ND * ND];
__device__ __align__(128) float g_Gp[(size_t)32 * CH * CH];
__device__ float g_s[NB * CH], g_u1[NB * ND], g_u2[NB * ND];

// ---------------- asm helpers ----------------------------------------------
__device__ __forceinline__ uint32_t smem_to_u32(const void* p) {
    uint32_t a;
    asm("{ .reg .u64 t; cvta.to.shared.u64 t, %1; cvt.u32.u64 %0, t; }"
        : "=r"(a) : "l"(p));
    return a;
}
#define CPA16(s, g) \
    asm volatile("cp.async.cg.shared.global [%0], [%1], 16;" :: "r"(s), "l"(g) : "memory")
#define CPA_COMMIT() asm volatile("cp.async.commit_group;" ::: "memory")
#define CPA_WAIT(n)  asm volatile("cp.async.wait_group %0;" :: "n"(n) : "memory")
#define LDSM4(r0, r1, r2, r3, addr) \
    asm volatile("ldmatrix.sync.aligned.m8n8.x4.shared.b16 {%0,%1,%2,%3}, [%4];" \
        : "=r"(r0), "=r"(r1), "=r"(r2), "=r"(r3) : "r"(addr))
#define MMA_F16(d, a, bb0, bb1) \
    asm volatile("mma.sync.aligned.m16n8k16.row.col.f32.f16.f16.f32 " \
        "{%0,%1,%2,%3}, {%4,%5,%6,%7}, {%8,%9}, {%0,%1,%2,%3};" \
        : "+f"((d)[0]), "+f"((d)[1]), "+f"((d)[2]), "+f"((d)[3]) \
        : "r"((a)[0]), "r"((a)[1]), "r"((a)[2]), "r"((a)[3]), "r"(bb0), "r"(bb1))

// ===========================================================================
// tc_gemm<NPA, NPB, NSTAGE, OMODE>: C[128x256/CTA], NT GEMM, K-contig.
// Products: a0.b0  (+ a1.b0 if NPA==2)  (+ a0.b1 if NPB==2).
// BK=64 (128B rows, swizzle chunk ^= row&7). NSTAGE-deep cp.async pipeline;
// NSTAGE>=3 uses a single __syncthreads per chunk.
// 8 warps as 2(M) x 4(N); warp tile 64x64; m16n8k16 f16 mma, fp32 accum.
// OMODE: 0 fp32; 2 fp32 + rank-2 e0[m]e1[n]+e2[m]e3[n];
//        4 2-plane fp16 split store (+bias e0[m]); 5 1-plane fp16 (+bias).
// Split-K via nsplit. Requires nch >= NSTAGE-1.
// ===========================================================================
#define TILE_A  16384           // 128 rows * 128 B
#define TILE_BB 32768           // 256 rows * 128 B

template<int NPA, int NPB, int NSTAGE, int OMODE>
__global__ void __launch_bounds__(256, 1)
tc_gemm(const h16* __restrict__ a0, const h16* __restrict__ a1,
        const h16* __restrict__ b0, const h16* __restrict__ b1,
        int Ksub, int nsplit, int lda, int ldb, long long sA, long long sB,
        float* __restrict__ Cf, h16* __restrict__ c0, h16* __restrict__ c1,
        int ldc, long long sC,
        const float* __restrict__ e0, long long se0,
        const float* __restrict__ e1, const float* __restrict__ e2,
        const float* __restrict__ e3, long long se3)
{
    constexpr int STB = NPA * TILE_A + NPB * TILE_BB;   // stage bytes
    extern __shared__ __align__(1024) char smem[];
    const uint32_t sb = smem_to_u32(smem);
    const int tid = threadIdx.x, wid = tid >> 5, lane = tid & 31;
    const int bx = blockIdx.x, by = blockIdx.y, z = blockIdx.z;
    const int bat = z / nsplit, sp = z - bat * nsplit;

    // ---- cp.async geometry
    const int rr = tid >> 3;                 // 0..31
    const int qq = tid & 7;                  // 0..7
    const uint32_t sw = (uint32_t)((qq ^ (rr & 7)) << 4);
    const long long koffB = (long long)sp * Ksub * 2;

    const char* gA[2];
    const char* gB[2];
    long long rstepA, rstepB;
    {
        const long long la2 = (long long)lda * 2, lb2 = (long long)ldb * 2;
        gA[0] = (const char*)(a0 + (long long)bat * sA)
              + (long long)(by * 128) * la2 + rr * la2 + qq * 16 + koffB;
        gA[1] = (NPA == 2)
              ? (const char*)(a1 + (long long)bat * sA)
                + (long long)(by * 128) * la2 + rr * la2 + qq * 16 + koffB
              : nullptr;
        gB[0] = (const char*)(b0 + (long long)bat * sB)
              + (long long)(bx * 256) * lb2 + rr * lb2 + qq * 16 + koffB;
        gB[1] = (NPB == 2)
              ? (const char*)(b1 + (long long)bat * sB)
                + (long long)(bx * 256) * lb2 + rr * lb2 + qq * 16 + koffB
              : nullptr;
        rstepA = la2 * 32;
        rstepB = lb2 * 32;
    }

    auto load_stage = [&](int ck, int stg) {
        const uint32_t s0 = sb + stg * STB;
        #pragma unroll
        for (int t = 0; t < NPA; t++) {
            #pragma unroll
            for (int jj = 0; jj < 4; jj++) {       // A: 128 rows
                const uint32_t sa = s0 + t * TILE_A
                                  + (uint32_t)((jj * 32 + rr) * 128) + sw;
                CPA16(sa, gA[t] + jj * rstepA + (long long)ck * 128);
            }
        }
        #pragma unroll
        for (int t = 0; t < NPB; t++) {
            #pragma unroll
            for (int jj = 0; jj < 8; jj++) {       // B: 256 rows
                const uint32_t sa = s0 + NPA * TILE_A + t * TILE_BB
                                  + (uint32_t)((jj * 32 + rr) * 128) + sw;
                CPA16(sa, gB[t] + jj * rstepB + (long long)ck * 128);
            }
        }
        CPA_COMMIT();
    };

    // ---- mma geometry: warps 2(M) x 4(N), warp tile 64x64
    const int mwarp = (wid & 1) * 64, nwarp = (wid >> 1) * 64;
    const int g8 = lane >> 3, id8 = lane & 7;
    const int aRow = ((g8 & 1) << 3) + id8, aC = g8 >> 1;
    const int bRow = (((g8 >> 1) & 1) << 3) + id8, bC = g8 & 1;

    float acc[128];
    #pragma unroll
    for (int i = 0; i < 128; i++) acc[i] = 0.f;

    auto compute_chunk = [&](int stg) {
        const uint32_t s0 = sb + stg * STB;
        const uint32_t at0 = s0, at1 = s0 + TILE_A;
        const uint32_t bt0 = s0 + NPA * TILE_A;
        const uint32_t bt1 = bt0 + TILE_BB;
        #pragma unroll
        for (int kk = 0; kk < 4; kk++) {
            const uint32_t aoff = (uint32_t)(((kk * 2 + aC) ^ id8) << 4);
            const uint32_t boff = (uint32_t)(((kk * 2 + bC) ^ id8) << 4);
            uint32_t a0f[4][4], a1f[4][4], bf[4][4];
            #pragma unroll
            for (int mt = 0; mt < 4; mt++) {
                const uint32_t mrow = (uint32_t)((mwarp + mt * 16 + aRow) * 128);
                LDSM4(a0f[mt][0], a0f[mt][1], a0f[mt][2], a0f[mt][3], at0 + mrow + aoff);
                if (NPA == 2)
                    LDSM4(a1f[mt][0], a1f[mt][1], a1f[mt][2], a1f[mt][3], at1 + mrow + aoff);
            }
            #pragma unroll
            for (int nt = 0; nt < 4; nt++) {
                const uint32_t nrow = (uint32_t)((nwarp + nt * 16 + bRow) * 128);
                LDSM4(bf[nt][0], bf[nt][1], bf[nt][2], bf[nt][3], bt0 + nrow + boff);
            }
            #pragma unroll
            for (int mt = 0; mt < 4; mt++)
                #pragma unroll
                for (int nt = 0; nt < 4; nt++) {
                    MMA_F16(&acc[(mt * 8 + nt * 2) * 4],     a0f[mt], bf[nt][0], bf[nt][1]);
                    MMA_F16(&acc[(mt * 8 + nt * 2 + 1) * 4], a0f[mt], bf[nt][2], bf[nt][3]);
                    if (NPA == 2) {
                        MMA_F16(&acc[(mt * 8 + nt * 2) * 4],     a1f[mt], bf[nt][0], bf[nt][1]);
                        MMA_F16(&acc[(mt * 8 + nt * 2 + 1) * 4], a1f[mt], bf[nt][2], bf[nt][3]);
                    }
                }
            if (NPB == 2) {
                #pragma unroll
                for (int nt = 0; nt < 4; nt++) {
                    const uint32_t nrow = (uint32_t)((nwarp + nt * 16 + bRow) * 128);
                    LDSM4(bf[nt][0], bf[nt][1], bf[nt][2], bf[nt][3], bt1 + nrow + boff);
                }
                #pragma unroll
                for (int mt = 0; mt < 4; mt++)
                    #pragma unroll
                    for (int nt = 0; nt < 4; nt++) {
                        MMA_F16(&acc[(mt * 8 + nt * 2) * 4],     a0f[mt], bf[nt][0], bf[nt][1]);
                        MMA_F16(&acc[(mt * 8 + nt * 2 + 1) * 4], a0f[mt], bf[nt][2], bf[nt][3]);
                    }
            }
        }
    };

    const int nch = Ksub >> 6;
    if constexpr (NSTAGE == 2) {
        load_stage(0, 0);
        for (int i = 0; i < nch; i++) {
            if (i + 1 < nch) { load_stage(i + 1, (i + 1) & 1); CPA_WAIT(1); }
            else             { CPA_WAIT(0); }
            __syncthreads();
            compute_chunk(i & 1);
            __syncthreads();
        }
    } else {
        #pragma unroll
        for (int p = 0; p < NSTAGE - 1; p++) load_stage(p, p);
        for (int i = 0; i < nch; i++) {
            CPA_WAIT(NSTAGE - 2);
            __syncthreads();
            compute_chunk(i % NSTAGE);
            const int nx = i + NSTAGE - 1;
            if (nx < nch) load_stage(nx, nx % NSTAGE);
            else         CPA_COMMIT();
        }
    }

    // ---- epilogue
    const int er = lane >> 2, ec = (lane & 3) * 2;
    const float* e0b = e0 ? (e0 + (long long)bat * se0) : nullptr;
    const float* e3b = e3 ? (e3 + (long long)bat * se3) : nullptr;
    float* Cz = Cf ? (Cf + (long long)z * sC) : nullptr;
    h16* c0z = c0 ? (c0 + (long long)z * sC) : nullptr;
    h16* c1z = c1 ? (c1 + (long long)z * sC) : nullptr;

    #pragma unroll
    for (int mt = 0; mt < 4; mt++) {
        #pragma unroll
        for (int h = 0; h < 2; h++) {
            const int m = by * 128 + mwarp + mt * 16 + er + h * 8;
            float rowadd0 = 0.f, rowadd1 = 0.f, bias = 0.f;
            if (OMODE == 2) { rowadd0 = e0b[m]; rowadd1 = e2[m]; }
            if ((OMODE == 4 || OMODE == 5) && e0) bias = e0b[m];
            #pragma unroll
            for (int nt8 = 0; nt8 < 8; nt8++) {
                const int n = bx * 256 + nwarp + nt8 * 8 + ec;
                float v0 = acc[(mt * 8 + nt8) * 4 + h * 2];
                float v1 = acc[(mt * 8 + nt8) * 4 + h * 2 + 1];
                if (OMODE == 2) {
                    v0 += rowadd0 * e1[n]     + rowadd1 * e3b[n];
                    v1 += rowadd0 * e1[n + 1] + rowadd1 * e3b[n + 1];
                }
                if (OMODE == 0 || OMODE == 2) {
                    *reinterpret_cast<float2*>(Cz + (size_t)m * ldc + n) =
                        make_float2(v0, v1);
                } else if (OMODE == 5) {
                    *reinterpret_cast<__half2*>(c0z + (size_t)m * ldc + n) =
                        __floats2half2_rn(v0 + bias, v1 + bias);
                } else {
                    v0 += bias; v1 += bias;
                    h16 h0a = __float2half(v0);
                    h16 h0b = __float2half(v1);
                    float r0 = v0 - __half2float(h0a);
                    float r1 = v1 - __half2float(h0b);
                    __half2 lo; lo.x = h0a; lo.y = h0b;
                    __half2 hi; hi.x = __float2half(r0); hi.y = __float2half(r1);
                    *reinterpret_cast<__half2*>(c0z + (size_t)m * ldc + n) = lo;
                    *reinterpret_cast<__half2*>(c1z + (size_t)m * ldc + n) = hi;
                }
            }
        }
    }
}

// ---------------- small kernels --------------------------------------------
__device__ __forceinline__ void split_store4(const float4 f, h16* p0, h16* p1, size_t i)
{
    const float v[4] = {f.x, f.y, f.z, f.w};
    __half2 lo[2], hi[2];
    #pragma unroll
    for (int q = 0; q < 2; q++) {
        h16 a0 = __float2half(v[q * 2]);
        h16 a1 = __float2half(v[q * 2 + 1]);
        lo[q].x = a0; lo[q].y = a1;
        hi[q].x = __float2half(v[q * 2]     - __half2float(a0));
        hi[q].y = __float2half(v[q * 2 + 1] - __half2float(a1));
    }
    reinterpret_cast<__half2*>(p0)[i * 2]     = lo[0];
    reinterpret_cast<__half2*>(p0)[i * 2 + 1] = lo[1];
    reinterpret_cast<__half2*>(p1)[i * 2]     = hi[0];
    reinterpret_cast<__half2*>(p1)[i * 2 + 1] = hi[1];
}

// Merged weight split: Wq | Wk | Wv, one float4 per thread (R12 form).
__global__ void wsplit_kernel(const float* __restrict__ Wq, h16* q0, h16* q1,
                              const float* __restrict__ Wk, h16* k0, h16* k1,
                              const float* __restrict__ Wv, h16* v0, h16* v1)
{
    constexpr size_t NQ4 = (size_t)ND * CH / 4;     // 524288
    constexpr size_t NV4 = (size_t)CH * CH / 4;     // 65536
    size_t i = (size_t)blockIdx.x * 256 + threadIdx.x;
    const float* src; h16 *p0, *p1; size_t j;
    if (i < NQ4)            { src = Wq; p0 = q0; p1 = q1; j = i; }
    else if (i < 2 * NQ4)   { src = Wk; p0 = k0; p1 = k1; j = i - NQ4; }
    else                    { src = Wv; p0 = v0; p1 = v1; j = i - 2 * NQ4;
                              if (j >= NV4) return; }
    split_store4(reinterpret_cast<const float4*>(src)[j], p0, p1, j);
}

// x-split with fused rowsum (warps never straddle a 1024-float4 row).
__global__ void split2_rowsum_kernel(const float* __restrict__ src,
                                     h16* __restrict__ p0, h16* __restrict__ p1,
                                     float* __restrict__ s, size_t n4)
{
    size_t i = (size_t)blockIdx.x * 256 + threadIdx.x;
    if (i >= n4) return;
    const float4 f = reinterpret_cast<const float4*>(src)[i];
    split_store4(f, p0, p1, i);
    float partial = (f.x + f.y) + (f.z + f.w);
    #pragma unroll
    for (int o = 16; o; o >>= 1) partial += __shfl_xor_sync(0xffffffffu, partial, o);
    if ((threadIdx.x & 31) == 0)
        atomicAdd(&s[i >> 10], partial);        // row = i / (ND/4)
}

__global__ void zero_kernel(float* __restrict__ p, int n)
{
    int i = blockIdx.x * 256 + threadIdx.x;
    if (i < n) p[i] = 0.f;
}

// Transpose x plane0 (fp16, already rounded) -> xt. Pure fp16 copy-transpose.
__global__ void transpose_kernel(const h16* __restrict__ X0, h16* __restrict__ t0)
{
    __shared__ h16 tile[32][34];
    const int n0 = blockIdx.x * 32, c0 = blockIdx.y * 32, b = blockIdx.z;
    const int tx = threadIdx.x, ty = threadIdx.y;   // 32 x 8
    const h16* Xb = X0 + (size_t)b * CH * ND;
    #pragma unroll
    for (int k = 0; k < 32; k += 8)
        tile[ty + k][tx] = Xb[(size_t)(c0 + ty + k) * ND + n0 + tx];
    __syncthreads();
    h16* d0 = t0 + (size_t)b * ND * CH;
    #pragma unroll
    for (int k = 0; k < 32; k += 8)
        d0[(size_t)(n0 + ty + k) * CH + c0 + tx] = tile[tx][ty + k];
}

__global__ void greduce_split_kernel(const float* __restrict__ Gp,
                                     h16* __restrict__ g0, h16* __restrict__ g1)
{
    const int bat = blockIdx.y;
    const int i = blockIdx.x * 256 + threadIdx.x;      // < 262144
    const float* p = Gp + ((size_t)bat * 8) * 262144 + i;
    float f = 0.f;
    #pragma unroll
    for (int s = 0; s < 8; s++) f += p[(size_t)s * 262144];
    const size_t o = (size_t)bat * 262144 + i;
    h16 a = __float2half(f);
    g0[o] = a;
    g1[o] = __float2half(f - __half2float(a));
}

// Merged gemv: z=0 -> u1 = Wq s + ND*bq ; z=1 -> u2 = Wk s.
__global__ __launch_bounds__(256)
void gemv2_kernel(const float* __restrict__ Wq, const float* __restrict__ bq,
                  const float* __restrict__ Wk,
                  const float* __restrict__ s,
                  float* __restrict__ u1, float* __restrict__ u2)
{
    const int bat = blockIdx.y;
    const int which = blockIdx.z;
    const float* W = which ? Wk : Wq;
    float* y = which ? u2 : u1;
    const int warp = threadIdx.x >> 5, lane = threadIdx.x & 31;
    const int row = blockIdx.x * 8 + warp;
    const float* sv = s + (size_t)bat * CH;
    const float* w = W + (size_t)row * CH;
    float acc = 0.f;
    for (int c = lane; c < CH; c += 32) acc += w[c] * sv[c];
    #pragma unroll
    for (int o = 16; o; o >>= 1) acc += __shfl_xor_sync(0xffffffffu, acc, o);
    if (lane == 0) {
        float b = which ? 0.f : (float)ND * bq[row];
        y[(size_t)bat * ND + row] = acc + b;
    }
}

// softmax over fp32 rows of E; writes P as ONE fp16 plane. float4 loads.
__global__ __launch_bounds__(256)
void softmax_split_kernel(const float* __restrict__ E, h16* __restrict__ p0)
{
    const size_t ro = ((size_t)blockIdx.y * ND + blockIdx.x) * ND;
    const float4* r = reinterpret_cast<const float4*>(E + ro);
    const int tid = threadIdx.x;
    float vals[16];
    float m = -1e30f;
    #pragma unroll
    for (int i = 0; i < 4; i++) {
        const float4 v = r[tid + i * 256];
        vals[i * 4]     = v.x; vals[i * 4 + 1] = v.y;
        vals[i * 4 + 2] = v.z; vals[i * 4 + 3] = v.w;
        m = fmaxf(m, fmaxf(fmaxf(v.x, v.y), fmaxf(v.z, v.w)));
    }
    __shared__ float sh[8];
    #pragma unroll
    for (int o = 16; o; o >>= 1) m = fmaxf(m, __shfl_xor_sync(0xffffffffu, m, o));
    if ((tid & 31) == 0) sh[tid >> 5] = m;
    __syncthreads();
    if (tid < 32) {
        float t = (tid < 8) ? sh[tid] : -1e30f;
        #pragma unroll
        for (int o = 4; o; o >>= 1) t = fmaxf(t, __shfl_xor_sync(0xffffffffu, t, o));
        if (tid == 0) sh[0] = t;
    }
    __syncthreads();
    m = sh[0];
    __syncthreads();
    float s = 0.f;
    #pragma unroll
    for (int i = 0; i < 16; i++) { vals[i] = __expf(vals[i] - m); s += vals[i]; }
    #pragma unroll
    for (int o = 16; o; o >>= 1) s += __shfl_xor_sync(0xffffffffu, s, o);
    if ((tid & 31) == 0) sh[tid >> 5] = s;
    __syncthreads();
    if (tid < 32) {
        float t = (tid < 8) ? sh[tid] : 0.f;
        #pragma unroll
        for (int o = 4; o; o >>= 1) t += __shfl_xor_sync(0xffffffffu, t, o);
        if (tid == 0) sh[0] = t;
    }
    __syncthreads();
    const float inv = 1.0f / sh[0];
    __half2* w0 = reinterpret_cast<__half2*>(p0 + ro);
    #pragma unroll
    for (int i = 0; i < 4; i++) {
        #pragma unroll
        for (int q = 0; q < 2; q++) {
            const int j = (tid + i * 256) * 2 + q;
            w0[j] = __floats2half2_rn(vals[i * 4 + q * 2] * inv,
                                      vals[i * 4 + q * 2 + 1] * inv);
        }
    }
}

// ---------------------------------------------------------------------------
extern "C" void kernel_launch(void* const* d_in, const int* in_sizes, int n_in,
                              void* d_out, int out_size)
{
    const float* x  = (const float*)d_in[0];
    const float* Wq = (const float*)d_in[1];
    const float* bq = (const float*)d_in[2];
    const float* Wk = (const float*)d_in[3];
    const float* bk = (const float*)d_in[4];
    const float* Wv = (const float*)d_in[5];
    const float* bv = (const float*)d_in[6];
    float* out = (float*)d_out;

    h16 *x0, *xt0, *wq0, *wk0, *wv0, *gg0, *kh0, *vv0, *pp0;
    float *E, *Gp, *s, *u1, *u2;
    cudaGetSymbolAddress((void**)&x0,  g_x);
    cudaGetSymbolAddress((void**)&xt0, g_xt);
    cudaGetSymbolAddress((void**)&wq0, g_wq);
    cudaGetSymbolAddress((void**)&wk0, g_wk);
    cudaGetSymbolAddress((void**)&wv0, g_wv);
    cudaGetSymbolAddress((void**)&gg0, g_gg);
    cudaGetSymbolAddress((void**)&kh0, g_kh);
    cudaGetSymbolAddress((void**)&vv0, g_vv);
    cudaGetSymbolAddress((void**)&pp0, g_pp);
    cudaGetSymbolAddress((void**)&E,  g_E);
    cudaGetSymbolAddress((void**)&Gp, g_Gp);
    cudaGetSymbolAddress((void**)&s,  g_s);
    cudaGetSymbolAddress((void**)&u1, g_u1);
    cudaGetSymbolAddress((void**)&u2, g_u2);

    const size_t PX = (size_t)NB * CH * ND;
    const size_t PW = (size_t)ND * CH;
    const size_t PV = (size_t)CH * CH;
    const size_t PG = (size_t)NB * CH * CH;
    const size_t PK = (size_t)NB * ND * CH;
    h16 *x1 = x0 + PX;
    h16 *wq1 = wq0 + PW, *wk1 = wk0 + PW, *wv1 = wv0 + PV;
    h16 *gg1 = gg0 + PG, *kh1 = kh0 + PK;

    const int SMEM = 196608;
    cudaFuncSetAttribute(tc_gemm<2,2,2,0>, cudaFuncAttributeMaxDynamicSharedMemorySize, SMEM);
    cudaFuncSetAttribute(tc_gemm<2,2,2,2>, cudaFuncAttributeMaxDynamicSharedMemorySize, SMEM);
    cudaFuncSetAttribute(tc_gemm<2,2,2,4>, cudaFuncAttributeMaxDynamicSharedMemorySize, SMEM);
    cudaFuncSetAttribute(tc_gemm<2,1,3,5>, cudaFuncAttributeMaxDynamicSharedMemorySize, SMEM);
    cudaFuncSetAttribute(tc_gemm<1,1,4,0>, cudaFuncAttributeMaxDynamicSharedMemorySize, SMEM);

    // prologue: s = 0; x split (+rowsum); transpose(fp16); weight splits; gemvs
    zero_kernel<<<8, 256>>>(s, NB * CH);
    split2_rowsum_kernel<<<(unsigned)(PX / 4 / 256), 256>>>(x, x0, x1, s, PX / 4);
    transpose_kernel<<<dim3(128, 16, NB), dim3(32, 8)>>>(x0, xt0);
    wsplit_kernel<<<(unsigned)((2 * PW / 4 + PV / 4 + 255) / 256), 256>>>(
        Wq, wq0, wq1, Wk, wk0, wk1, Wv, wv0, wv1);
    gemv2_kernel<<<dim3(ND / 8, NB, 2), 256>>>(Wq, bq, Wk, s, u1, u2);

    const long long sX = (long long)CH * ND;
    const long long sG = (long long)CH * CH;
    const long long sK = (long long)ND * CH;
    const long long sE = (long long)ND * ND;

    // G_b = X X^T  (split-K 8, fp32 partials), then reduce + split
    tc_gemm<2,2,2,0><<<dim3(2, 4, 32), 256, SMEM>>>(
        x0, x1, x0, x1, 512, 8, ND, ND, sX, sX,
        Gp, nullptr, nullptr, CH, sG,
        nullptr, 0, nullptr, nullptr, nullptr, 0);
    greduce_split_kernel<<<dim3(1024, NB), 256>>>(Gp, gg0, gg1);

    // Khat_b = Wk G_b  (G symmetric -> NT), split2 output
    tc_gemm<2,2,2,4><<<dim3(2, 32, NB), 256, SMEM>>>(
        wk0, wk1, gg0, gg1, CH, 1, CH, CH, 0, sG,
        nullptr, kh0, kh1, CH, sK,
        nullptr, 0, nullptr, nullptr, nullptr, 0);

    // V_b = Wv X_b + bv  (B = xt single plane), 2 products, 3-stage
    tc_gemm<2,1,3,5><<<dim3(16, 4, NB), 256, SMEM>>>(
        wv0, wv1, xt0, nullptr, CH, 1, CH, CH, 0, sK,
        nullptr, vv0, nullptr, ND, sX,
        bv, 0, nullptr, nullptr, nullptr, 0);

    // E_b = Wq Khat^T + u1 bk^T + bq u2^T, fp32 + rank-2 (batched)
    tc_gemm<2,2,2,2><<<dim3(16, 32, NB), 256, SMEM>>>(
        wq0, wq1, kh0, kh1, CH, 1, CH, CH, 0, sK,
        E, nullptr, nullptr, ND, sE,
        u1, ND, bk, bq, u2, ND);

    // P = softmax(E) -> ONE fp16 plane (batched)
    softmax_split_kernel<<<dim3(ND, NB), 256>>>(E, pp0);

    // out_b = V_b P_b^T, 1 product, 4-stage, fp32
    tc_gemm<1,1,4,0><<<dim3(16, 4, NB), 256, SMEM>>>(
        vv0, nullptr, pp0, nullptr, ND, 1, ND, ND, sX, sE,
        out, nullptr, nullptr, ND, sX,
        nullptr, 0, nullptr, nullptr, nullptr, 0);
}

// round 16
// speedup vs baseline: 1.0096x; 1.0040x over previous
#include <cuda_runtime.h>
#include <cuda_fp16.h>
#include <cstdint>
#include <cstddef>

// ===========================================================================
// HyperNodeAggregation via mma.sync fp16 multi-product GEMMs (fp32 accum).
//   E_b = Wq (Wk G_b)^T + u1 bk^T + bq u2^T,  G_b = X X^T (symmetric)
//   P = softmax(E);  V = Wv X + bv 1^T;  out = V P^T
// fp32 operands split into 2 fp16 planes (residual 2^-11).
// Products: logit chain (G, Khat, E) = 3;  V = 2;  out = 1.
// R16: separate b1 fragment registers — all 12 LDSM per kk issued up-front,
//      removing the WAR serialization before the a0.b1 product.
// ===========================================================================

using h16 = __half;

constexpr int NB = 4, CH = 512, ND = 4096;

// ---------------- scratch (device globals; allocation-free rule) -----------
__device__ __align__(128) h16 g_x [2][(size_t)NB * CH * ND];
__device__ __align__(128) h16 g_xt[(size_t)NB * ND * CH];      // single plane
__device__ __align__(128) h16 g_wq[2][(size_t)ND * CH];
__device__ __align__(128) h16 g_wk[2][(size_t)ND * CH];
__device__ __align__(128) h16 g_wv[2][(size_t)CH * CH];
__device__ __align__(128) h16 g_gg[2][(size_t)NB * CH * CH];
__device__ __align__(128) h16 g_kh[2][(size_t)NB * ND * CH];
__device__ __align__(128) h16 g_vv[(size_t)NB * CH * ND];      // single plane
__device__ __align__(128) h16 g_pp[(size_t)NB * ND * ND];      // single plane
__device__ __align__(128) float g_E [(size_t)NB * ND * ND];
__device__ __align__(128) float g_Gp[(size_t)32 * CH * CH];
__device__ float g_s[NB * CH], g_u1[NB * ND], g_u2[NB * ND];

// ---------------- asm helpers ----------------------------------------------
__device__ __forceinline__ uint32_t smem_to_u32(const void* p) {
    uint32_t a;
    asm("{ .reg .u64 t; cvta.to.shared.u64 t, %1; cvt.u32.u64 %0, t; }"
        : "=r"(a) : "l"(p));
    return a;
}
#define CPA16(s, g) \
    asm volatile("cp.async.cg.shared.global [%0], [%1], 16;" :: "r"(s), "l"(g) : "memory")
#define CPA_COMMIT() asm volatile("cp.async.commit_group;" ::: "memory")
#define CPA_WAIT(n)  asm volatile("cp.async.wait_group %0;" :: "n"(n) : "memory")
#define LDSM4(r0, r1, r2, r3, addr) \
    asm volatile("ldmatrix.sync.aligned.m8n8.x4.shared.b16 {%0,%1,%2,%3}, [%4];" \
        : "=r"(r0), "=r"(r1), "=r"(r2), "=r"(r3) : "r"(addr))
#define MMA_F16(d, a, bb0, bb1) \
    asm volatile("mma.sync.aligned.m16n8k16.row.col.f32.f16.f16.f32 " \
        "{%0,%1,%2,%3}, {%4,%5,%6,%7}, {%8,%9}, {%0,%1,%2,%3};" \
        : "+f"((d)[0]), "+f"((d)[1]), "+f"((d)[2]), "+f"((d)[3]) \
        : "r"((a)[0]), "r"((a)[1]), "r"((a)[2]), "r"((a)[3]), "r"(bb0), "r"(bb1))

// ===========================================================================
// tc_gemm<NPA, NPB, NSTAGE, OMODE>: C[128x256/CTA], NT GEMM, K-contig.
// Products: a0.b0  (+ a1.b0 if NPA==2)  (+ a0.b1 if NPB==2).
// BK=64 (128B rows, swizzle chunk ^= row&7). NSTAGE-deep cp.async pipeline;
// NSTAGE>=3 uses a single __syncthreads per chunk.
// 8 warps as 2(M) x 4(N); warp tile 64x64; m16n8k16 f16 mma, fp32 accum.
// All fragments (incl. b1) loaded up-front per kk to overlap LDSM latency.
// OMODE: 0 fp32; 2 fp32 + rank-2 e0[m]e1[n]+e2[m]e3[n];
//        4 2-plane fp16 split store (+bias e0[m]); 5 1-plane fp16 (+bias).
// Split-K via nsplit. Requires nch >= NSTAGE-1.
// ===========================================================================
#define TILE_A  16384           // 128 rows * 128 B
#define TILE_BB 32768           // 256 rows * 128 B

template<int NPA, int NPB, int NSTAGE, int OMODE>
__global__ void __launch_bounds__(256, 1)
tc_gemm(const h16* __restrict__ a0, const h16* __restrict__ a1,
        const h16* __restrict__ b0, const h16* __restrict__ b1,
        int Ksub, int nsplit, int lda, int ldb, long long sA, long long sB,
        float* __restrict__ Cf, h16* __restrict__ c0, h16* __restrict__ c1,
        int ldc, long long sC,
        const float* __restrict__ e0, long long se0,
        const float* __restrict__ e1, const float* __restrict__ e2,
        const float* __restrict__ e3, long long se3)
{
    constexpr int STB = NPA * TILE_A + NPB * TILE_BB;   // stage bytes
    extern __shared__ __align__(1024) char smem[];
    const uint32_t sb = smem_to_u32(smem);
    const int tid = threadIdx.x, wid = tid >> 5, lane = tid & 31;
    const int bx = blockIdx.x, by = blockIdx.y, z = blockIdx.z;
    const int bat = z / nsplit, sp = z - bat * nsplit;

    // ---- cp.async geometry
    const int rr = tid >> 3;                 // 0..31
    const int qq = tid & 7;                  // 0..7
    const uint32_t sw = (uint32_t)((qq ^ (rr & 7)) << 4);
    const long long koffB = (long long)sp * Ksub * 2;

    const char* gA[2];
    const char* gB[2];
    long long rstepA, rstepB;
    {
        const long long la2 = (long long)lda * 2, lb2 = (long long)ldb * 2;
        gA[0] = (const char*)(a0 + (long long)bat * sA)
              + (long long)(by * 128) * la2 + rr * la2 + qq * 16 + koffB;
        gA[1] = (NPA == 2)
              ? (const char*)(a1 + (long long)bat * sA)
                + (long long)(by * 128) * la2 + rr * la2 + qq * 16 + koffB
              : nullptr;
        gB[0] = (const char*)(b0 + (long long)bat * sB)
              + (long long)(bx * 256) * lb2 + rr * lb2 + qq * 16 + koffB;
        gB[1] = (NPB == 2)
              ? (const char*)(b1 + (long long)bat * sB)
                + (long long)(bx * 256) * lb2 + rr * lb2 + qq * 16 + koffB
              : nullptr;
        rstepA = la2 * 32;
        rstepB = lb2 * 32;
    }

    auto load_stage = [&](int ck, int stg) {
        const uint32_t s0 = sb + stg * STB;
        #pragma unroll
        for (int t = 0; t < NPA; t++) {
            #pragma unroll
            for (int jj = 0; jj < 4; jj++) {       // A: 128 rows
                const uint32_t sa = s0 + t * TILE_A
                                  + (uint32_t)((jj * 32 + rr) * 128) + sw;
                CPA16(sa, gA[t] + jj * rstepA + (long long)ck * 128);
            }
        }
        #pragma unroll
        for (int t = 0; t < NPB; t++) {
            #pragma unroll
            for (int jj = 0; jj < 8; jj++) {       // B: 256 rows
                const uint32_t sa = s0 + NPA * TILE_A + t * TILE_BB
                                  + (uint32_t)((jj * 32 + rr) * 128) + sw;
                CPA16(sa, gB[t] + jj * rstepB + (long long)ck * 128);
            }
        }
        CPA_COMMIT();
    };

    // ---- mma geometry: warps 2(M) x 4(N), warp tile 64x64
    const int mwarp = (wid & 1) * 64, nwarp = (wid >> 1) * 64;
    const int g8 = lane >> 3, id8 = lane & 7;
    const int aRow = ((g8 & 1) << 3) + id8, aC = g8 >> 1;
    const int bRow = (((g8 >> 1) & 1) << 3) + id8, bC = g8 & 1;

    float acc[128];
    #pragma unroll
    for (int i = 0; i < 128; i++) acc[i] = 0.f;

    auto compute_chunk = [&](int stg) {
        const uint32_t s0 = sb + stg * STB;
        const uint32_t at0 = s0, at1 = s0 + TILE_A;
        const uint32_t bt0 = s0 + NPA * TILE_A;
        const uint32_t bt1 = bt0 + TILE_BB;
        #pragma unroll
        for (int kk = 0; kk < 4; kk++) {
            const uint32_t aoff = (uint32_t)(((kk * 2 + aC) ^ id8) << 4);
            const uint32_t boff = (uint32_t)(((kk * 2 + bC) ^ id8) << 4);
            uint32_t a0f[4][4], a1f[4][4], bf[4][4], bf1[4][4];
            // ---- all LDSMs for this kk issued up-front (no WAR on bf1)
            #pragma unroll
            for (int mt = 0; mt < 4; mt++) {
                const uint32_t mrow = (uint32_t)((mwarp + mt * 16 + aRow) * 128);
                LDSM4(a0f[mt][0], a0f[mt][1], a0f[mt][2], a0f[mt][3], at0 + mrow + aoff);
                if (NPA == 2)
                    LDSM4(a1f[mt][0], a1f[mt][1], a1f[mt][2], a1f[mt][3], at1 + mrow + aoff);
            }
            #pragma unroll
            for (int nt = 0; nt < 4; nt++) {
                const uint32_t nrow = (uint32_t)((nwarp + nt * 16 + bRow) * 128);
                LDSM4(bf[nt][0], bf[nt][1], bf[nt][2], bf[nt][3], bt0 + nrow + boff);
                if (NPB == 2)
                    LDSM4(bf1[nt][0], bf1[nt][1], bf1[nt][2], bf1[nt][3], bt1 + nrow + boff);
            }
            // ---- products a0.b0 (+ a1.b0) — accumulation order unchanged
            #pragma unroll
            for (int mt = 0; mt < 4; mt++)
                #pragma unroll
                for (int nt = 0; nt < 4; nt++) {
                    MMA_F16(&acc[(mt * 8 + nt * 2) * 4],     a0f[mt], bf[nt][0], bf[nt][1]);
                    MMA_F16(&acc[(mt * 8 + nt * 2 + 1) * 4], a0f[mt], bf[nt][2], bf[nt][3]);
                    if (NPA == 2) {
                        MMA_F16(&acc[(mt * 8 + nt * 2) * 4],     a1f[mt], bf[nt][0], bf[nt][1]);
                        MMA_F16(&acc[(mt * 8 + nt * 2 + 1) * 4], a1f[mt], bf[nt][2], bf[nt][3]);
                    }
                }
            // ---- product a0.b1
            if (NPB == 2) {
                #pragma unroll
                for (int mt = 0; mt < 4; mt++)
                    #pragma unroll
                    for (int nt = 0; nt < 4; nt++) {
                        MMA_F16(&acc[(mt * 8 + nt * 2) * 4],     a0f[mt], bf1[nt][0], bf1[nt][1]);
                        MMA_F16(&acc[(mt * 8 + nt * 2 + 1) * 4], a0f[mt], bf1[nt][2], bf1[nt][3]);
                    }
            }
        }
    };

    const int nch = Ksub >> 6;
    if constexpr (NSTAGE == 2) {
        load_stage(0, 0);
        for (int i = 0; i < nch; i++) {
            if (i + 1 < nch) { load_stage(i + 1, (i + 1) & 1); CPA_WAIT(1); }
            else             { CPA_WAIT(0); }
            __syncthreads();
            compute_chunk(i & 1);
            __syncthreads();
        }
    } else {
        #pragma unroll
        for (int p = 0; p < NSTAGE - 1; p++) load_stage(p, p);
        for (int i = 0; i < nch; i++) {
            CPA_WAIT(NSTAGE - 2);
            __syncthreads();
            compute_chunk(i % NSTAGE);
            const int nx = i + NSTAGE - 1;
            if (nx < nch) load_stage(nx, nx % NSTAGE);
            else         CPA_COMMIT();
        }
    }

    // ---- epilogue
    const int er = lane >> 2, ec = (lane & 3) * 2;
    const float* e0b = e0 ? (e0 + (long long)bat * se0) : nullptr;
    const float* e3b = e3 ? (e3 + (long long)bat * se3) : nullptr;
    float* Cz = Cf ? (Cf + (long long)z * sC) : nullptr;
    h16* c0z = c0 ? (c0 + (long long)z * sC) : nullptr;
    h16* c1z = c1 ? (c1 + (long long)z * sC) : nullptr;

    #pragma unroll
    for (int mt = 0; mt < 4; mt++) {
        #pragma unroll
        for (int h = 0; h < 2; h++) {
            const int m = by * 128 + mwarp + mt * 16 + er + h * 8;
            float rowadd0 = 0.f, rowadd1 = 0.f, bias = 0.f;
            if (OMODE == 2) { rowadd0 = e0b[m]; rowadd1 = e2[m]; }
            if ((OMODE == 4 || OMODE == 5) && e0) bias = e0b[m];
            #pragma unroll
            for (int nt8 = 0; nt8 < 8; nt8++) {
                const int n = bx * 256 + nwarp + nt8 * 8 + ec;
                float v0 = acc[(mt * 8 + nt8) * 4 + h * 2];
                float v1 = acc[(mt * 8 + nt8) * 4 + h * 2 + 1];
                if (OMODE == 2) {
                    v0 += rowadd0 * e1[n]     + rowadd1 * e3b[n];
                    v1 += rowadd0 * e1[n + 1] + rowadd1 * e3b[n + 1];
                }
                if (OMODE == 0 || OMODE == 2) {
                    *reinterpret_cast<float2*>(Cz + (size_t)m * ldc + n) =
                        make_float2(v0, v1);
                } else if (OMODE == 5) {
                    *reinterpret_cast<__half2*>(c0z + (size_t)m * ldc + n) =
                        __floats2half2_rn(v0 + bias, v1 + bias);
                } else {
                    v0 += bias; v1 += bias;
                    h16 h0a = __float2half(v0);
                    h16 h0b = __float2half(v1);
                    float r0 = v0 - __half2float(h0a);
                    float r1 = v1 - __half2float(h0b);
                    __half2 lo; lo.x = h0a; lo.y = h0b;
                    __half2 hi; hi.x = __float2half(r0); hi.y = __float2half(r1);
                    *reinterpret_cast<__half2*>(c0z + (size_t)m * ldc + n) = lo;
                    *reinterpret_cast<__half2*>(c1z + (size_t)m * ldc + n) = hi;
                }
            }
        }
    }
}

// ---------------- small kernels --------------------------------------------
__device__ __forceinline__ void split_store4(const float4 f, h16* p0, h16* p1, size_t i)
{
    const float v[4] = {f.x, f.y, f.z, f.w};
    __half2 lo[2], hi[2];
    #pragma unroll
    for (int q = 0; q < 2; q++) {
        h16 a0 = __float2half(v[q * 2]);
        h16 a1 = __float2half(v[q * 2 + 1]);
        lo[q].x = a0; lo[q].y = a1;
        hi[q].x = __float2half(v[q * 2]     - __half2float(a0));
        hi[q].y = __float2half(v[q * 2 + 1] - __half2float(a1));
    }
    reinterpret_cast<__half2*>(p0)[i * 2]     = lo[0];
    reinterpret_cast<__half2*>(p0)[i * 2 + 1] = lo[1];
    reinterpret_cast<__half2*>(p1)[i * 2]     = hi[0];
    reinterpret_cast<__half2*>(p1)[i * 2 + 1] = hi[1];
}

// Merged weight split: Wq | Wk | Wv, one float4 per thread.
__global__ void wsplit_kernel(const float* __restrict__ Wq, h16* q0, h16* q1,
                              const float* __restrict__ Wk, h16* k0, h16* k1,
                              const float* __restrict__ Wv, h16* v0, h16* v1)
{
    constexpr size_t NQ4 = (size_t)ND * CH / 4;     // 524288
    constexpr size_t NV4 = (size_t)CH * CH / 4;     // 65536
    size_t i = (size_t)blockIdx.x * 256 + threadIdx.x;
    const float* src; h16 *p0, *p1; size_t j;
    if (i < NQ4)            { src = Wq; p0 = q0; p1 = q1; j = i; }
    else if (i < 2 * NQ4)   { src = Wk; p0 = k0; p1 = k1; j = i - NQ4; }
    else                    { src = Wv; p0 = v0; p1 = v1; j = i - 2 * NQ4;
                              if (j >= NV4) return; }
    split_store4(reinterpret_cast<const float4*>(src)[j], p0, p1, j);
}

// x-split with fused rowsum (warps never straddle a 1024-float4 row).
__global__ void split2_rowsum_kernel(const float* __restrict__ src,
                                     h16* __restrict__ p0, h16* __restrict__ p1,
                                     float* __restrict__ s, size_t n4)
{
    size_t i = (size_t)blockIdx.x * 256 + threadIdx.x;
    if (i >= n4) return;
    const float4 f = reinterpret_cast<const float4*>(src)[i];
    split_store4(f, p0, p1, i);
    float partial = (f.x + f.y) + (f.z + f.w);
    #pragma unroll
    for (int o = 16; o; o >>= 1) partial += __shfl_xor_sync(0xffffffffu, partial, o);
    if ((threadIdx.x & 31) == 0)
        atomicAdd(&s[i >> 10], partial);        // row = i / (ND/4)
}

__global__ void zero_kernel(float* __restrict__ p, int n)
{
    int i = blockIdx.x * 256 + threadIdx.x;
    if (i < n) p[i] = 0.f;
}

// Transpose x plane0 (fp16, already rounded) -> xt. Pure fp16 copy-transpose.
__global__ void transpose_kernel(const h16* __restrict__ X0, h16* __restrict__ t0)
{
    __shared__ h16 tile[32][34];
    const int n0 = blockIdx.x * 32, c0 = blockIdx.y * 32, b = blockIdx.z;
    const int tx = threadIdx.x, ty = threadIdx.y;   // 32 x 8
    const h16* Xb = X0 + (size_t)b * CH * ND;
    #pragma unroll
    for (int k = 0; k < 32; k += 8)
        tile[ty + k][tx] = Xb[(size_t)(c0 + ty + k) * ND + n0 + tx];
    __syncthreads();
    h16* d0 = t0 + (size_t)b * ND * CH;
    #pragma unroll
    for (int k = 0; k < 32; k += 8)
        d0[(size_t)(n0 + ty + k) * CH + c0 + tx] = tile[tx][ty + k];
}

__global__ void greduce_split_kernel(const float* __restrict__ Gp,
                                     h16* __restrict__ g0, h16* __restrict__ g1)
{
    const int bat = blockIdx.y;
    const int i = blockIdx.x * 256 + threadIdx.x;      // < 262144
    const float* p = Gp + ((size_t)bat * 8) * 262144 + i;
    float f = 0.f;
    #pragma unroll
    for (int s = 0; s < 8; s++) f += p[(size_t)s * 262144];
    const size_t o = (size_t)bat * 262144 + i;
    h16 a = __float2half(f);
    g0[o] = a;
    g1[o] = __float2half(f - __half2float(a));
}

// Merged gemv: z=0 -> u1 = Wq s + ND*bq ; z=1 -> u2 = Wk s.
__global__ __launch_bounds__(256)
void gemv2_kernel(const float* __restrict__ Wq, const float* __restrict__ bq,
                  const float* __restrict__ Wk,
                  const float* __restrict__ s,
                  float* __restrict__ u1, float* __restrict__ u2)
{
    const int bat = blockIdx.y;
    const int which = blockIdx.z;
    const float* W = which ? Wk : Wq;
    float* y = which ? u2 : u1;
    const int warp = threadIdx.x >> 5, lane = threadIdx.x & 31;
    const int row = blockIdx.x * 8 + warp;
    const float* sv = s + (size_t)bat * CH;
    const float* w = W + (size_t)row * CH;
    float acc = 0.f;
    for (int c = lane; c < CH; c += 32) acc += w[c] * sv[c];
    #pragma unroll
    for (int o = 16; o; o >>= 1) acc += __shfl_xor_sync(0xffffffffu, acc, o);
    if (lane == 0) {
        float b = which ? 0.f : (float)ND * bq[row];
        y[(size_t)bat * ND + row] = acc + b;
    }
}

// softmax over fp32 rows of E; writes P as ONE fp16 plane. float4 loads.
__global__ __launch_bounds__(256)
void softmax_split_kernel(const float* __restrict__ E, h16* __restrict__ p0)
{
    const size_t ro = ((size_t)blockIdx.y * ND + blockIdx.x) * ND;
    const float4* r = reinterpret_cast<const float4*>(E + ro);
    const int tid = threadIdx.x;
    float vals[16];
    float m = -1e30f;
    #pragma unroll
    for (int i = 0; i < 4; i++) {
        const float4 v = r[tid + i * 256];
        vals[i * 4]     = v.x; vals[i * 4 + 1] = v.y;
        vals[i * 4 + 2] = v.z; vals[i * 4 + 3] = v.w;
        m = fmaxf(m, fmaxf(fmaxf(v.x, v.y), fmaxf(v.z, v.w)));
    }
    __shared__ float sh[8];
    #pragma unroll
    for (int o = 16; o; o >>= 1) m = fmaxf(m, __shfl_xor_sync(0xffffffffu, m, o));
    if ((tid & 31) == 0) sh[tid >> 5] = m;
    __syncthreads();
    if (tid < 32) {
        float t = (tid < 8) ? sh[tid] : -1e30f;
        #pragma unroll
        for (int o = 4; o; o >>= 1) t = fmaxf(t, __shfl_xor_sync(0xffffffffu, t, o));
        if (tid == 0) sh[0] = t;
    }
    __syncthreads();
    m = sh[0];
    __syncthreads();
    float s = 0.f;
    #pragma unroll
    for (int i = 0; i < 16; i++) { vals[i] = __expf(vals[i] - m); s += vals[i]; }
    #pragma unroll
    for (int o = 16; o; o >>= 1) s += __shfl_xor_sync(0xffffffffu, s, o);
    if ((tid & 31) == 0) sh[tid >> 5] = s;
    __syncthreads();
    if (tid < 32) {
        float t = (tid < 8) ? sh[tid] : 0.f;
        #pragma unroll
        for (int o = 4; o; o >>= 1) t += __shfl_xor_sync(0xffffffffu, t, o);
        if (tid == 0) sh[0] = t;
    }
    __syncthreads();
    const float inv = 1.0f / sh[0];
    __half2* w0 = reinterpret_cast<__half2*>(p0 + ro);
    #pragma unroll
    for (int i = 0; i < 4; i++) {
        #pragma unroll
        for (int q = 0; q < 2; q++) {
            const int j = (tid + i * 256) * 2 + q;
            w0[j] = __floats2half2_rn(vals[i * 4 + q * 2] * inv,
                                      vals[i * 4 + q * 2 + 1] * inv);
        }
    }
}

// ---------------------------------------------------------------------------
extern "C" void kernel_launch(void* const* d_in, const int* in_sizes, int n_in,
                              void* d_out, int out_size)
{
    const float* x  = (const float*)d_in[0];
    const float* Wq = (const float*)d_in[1];
    const float* bq = (const float*)d_in[2];
    const float* Wk = (const float*)d_in[3];
    const float* bk = (const float*)d_in[4];
    const float* Wv = (const float*)d_in[5];
    const float* bv = (const float*)d_in[6];
    float* out = (float*)d_out;

    h16 *x0, *xt0, *wq0, *wk0, *wv0, *gg0, *kh0, *vv0, *pp0;
    float *E, *Gp, *s, *u1, *u2;
    cudaGetSymbolAddress((void**)&x0,  g_x);
    cudaGetSymbolAddress((void**)&xt0, g_xt);
    cudaGetSymbolAddress((void**)&wq0, g_wq);
    cudaGetSymbolAddress((void**)&wk0, g_wk);
    cudaGetSymbolAddress((void**)&wv0, g_wv);
    cudaGetSymbolAddress((void**)&gg0, g_gg);
    cudaGetSymbolAddress((void**)&kh0, g_kh);
    cudaGetSymbolAddress((void**)&vv0, g_vv);
    cudaGetSymbolAddress((void**)&pp0, g_pp);
    cudaGetSymbolAddress((void**)&E,  g_E);
    cudaGetSymbolAddress((void**)&Gp, g_Gp);
    cudaGetSymbolAddress((void**)&s,  g_s);
    cudaGetSymbolAddress((void**)&u1, g_u1);
    cudaGetSymbolAddress((void**)&u2, g_u2);

    const size_t PX = (size_t)NB * CH * ND;
    const size_t PW = (size_t)ND * CH;
    const size_t PV = (size_t)CH * CH;
    const size_t PG = (size_t)NB * CH * CH;
    const size_t PK = (size_t)NB * ND * CH;
    h16 *x1 = x0 + PX;
    h16 *wq1 = wq0 + PW, *wk1 = wk0 + PW, *wv1 = wv0 + PV;
    h16 *gg1 = gg0 + PG, *kh1 = kh0 + PK;

    const int SMEM = 196608;
    cudaFuncSetAttribute(tc_gemm<2,2,2,0>, cudaFuncAttributeMaxDynamicSharedMemorySize, SMEM);
    cudaFuncSetAttribute(tc_gemm<2,2,2,2>, cudaFuncAttributeMaxDynamicSharedMemorySize, SMEM);
    cudaFuncSetAttribute(tc_gemm<2,2,2,4>, cudaFuncAttributeMaxDynamicSharedMemorySize, SMEM);
    cudaFuncSetAttribute(tc_gemm<2,1,3,5>, cudaFuncAttributeMaxDynamicSharedMemorySize, SMEM);
    cudaFuncSetAttribute(tc_gemm<1,1,4,0>, cudaFuncAttributeMaxDynamicSharedMemorySize, SMEM);

    // prologue: s = 0; x split (+rowsum); transpose(fp16); weight splits; gemvs
    zero_kernel<<<8, 256>>>(s, NB * CH);
    split2_rowsum_kernel<<<(unsigned)(PX / 4 / 256), 256>>>(x, x0, x1, s, PX / 4);
    transpose_kernel<<<dim3(128, 16, NB), dim3(32, 8)>>>(x0, xt0);
    wsplit_kernel<<<(unsigned)((2 * PW / 4 + PV / 4 + 255) / 256), 256>>>(
        Wq, wq0, wq1, Wk, wk0, wk1, Wv, wv0, wv1);
    gemv2_kernel<<<dim3(ND / 8, NB, 2), 256>>>(Wq, bq, Wk, s, u1, u2);

    const long long sX = (long long)CH * ND;
    const long long sG = (long long)CH * CH;
    const long long sK = (long long)ND * CH;
    const long long sE = (long long)ND * ND;

    // G_b = X X^T  (split-K 8, fp32 partials), then reduce + split
    tc_gemm<2,2,2,0><<<dim3(2, 4, 32), 256, SMEM>>>(
        x0, x1, x0, x1, 512, 8, ND, ND, sX, sX,
        Gp, nullptr, nullptr, CH, sG,
        nullptr, 0, nullptr, nullptr, nullptr, 0);
    greduce_split_kernel<<<dim3(1024, NB), 256>>>(Gp, gg0, gg1);

    // Khat_b = Wk G_b  (G symmetric -> NT), split2 output
    tc_gemm<2,2,2,4><<<dim3(2, 32, NB), 256, SMEM>>>(
        wk0, wk1, gg0, gg1, CH, 1, CH, CH, 0, sG,
        nullptr, kh0, kh1, CH, sK,
        nullptr, 0, nullptr, nullptr, nullptr, 0);

    // V_b = Wv X_b + bv  (B = xt single plane), 2 products, 3-stage
    tc_gemm<2,1,3,5><<<dim3(16, 4, NB), 256, SMEM>>>(
        wv0, wv1, xt0, nullptr, CH, 1, CH, CH, 0, sK,
        nullptr, vv0, nullptr, ND, sX,
        bv, 0, nullptr, nullptr, nullptr, 0);

    // E_b = Wq Khat^T + u1 bk^T + bq u2^T, fp32 + rank-2 (batched)
    tc_gemm<2,2,2,2><<<dim3(16, 32, NB), 256, SMEM>>>(
        wq0, wq1, kh0, kh1, CH, 1, CH, CH, 0, sK,
        E, nullptr, nullptr, ND, sE,
        u1, ND, bk, bq, u2, ND);

    // P = softmax(E) -> ONE fp16 plane (batched)
    softmax_split_kernel<<<dim3(ND, NB), 256>>>(E, pp0);

    // out_b = V_b P_b^T, 1 product, 4-stage, fp32
    tc_gemm<1,1,4,0><<<dim3(16, 4, NB), 256, SMEM>>>(
        vv0, nullptr, pp0, nullptr, ND, 1, ND, ND, sX, sE,
        out, nullptr, nullptr, ND, sX,
        nullptr, 0, nullptr, nullptr, nullptr, 0);
}